// round 14
// baseline (speedup 1.0000x reference)
#include <cuda_runtime.h>
#include <cuda_fp16.h>
#include <cstdint>
#include <math.h>

// Problem constants
#define BATCH 16
#define SEQ   2048
#define DIM   512
#define NQKV  1536
#define MROWS (BATCH * SEQ)   // 32768
#define SCALE 0.125f

// GEMM tile config: CTA 256x128, BK=32, 512 threads (16 warps, 4x4), warp 64x32
#define BM 256
#define BN 128
#define BK 32
#define NTH 512

#define SROW 40                      // halves per row (32 + 8 pad)
#define O_AH 0
#define O_AL (BM * SROW * 2)         // 20480
#define O_BH (2 * BM * SROW * 2)     // 40960
#define O_BL (O_BH + BN * SROW * 2)  // 51200
#define STAGE_BYTES (O_BL + BN * SROW * 2)   // 61440
#define NSTAGES 3
#define SMEM_BYTES (NSTAGES * STAGE_BYTES)   // 184320

// Precision schemes for compute_tile
#define PX_HI  0   // aH*bH only
#define PX_X3  1   // aL*bH + aH*bL + aH*bH
#define PX_BL  2   // aH*bL + aH*bH  (no A-lo)

// ---------------------------------------------------------------------------
// Scratch (device globals — no allocation allowed)
// ---------------------------------------------------------------------------
__device__ __half g_xH[(size_t)MROWS * DIM];
__device__ __half g_xL[(size_t)MROWS * DIM];
__device__ __half g_wH[(size_t)NQKV * DIM];
__device__ __half g_wL[(size_t)NQKV * DIM];
__device__ float  g_bias[NQKV];
__device__ __half g_qkvH[(size_t)MROWS * NQKV];
__device__ __half g_qkvL[(size_t)MROWS * NQKV];
__device__ __half g_vtH[(size_t)MROWS * DIM];
__device__ __half g_vtL[(size_t)MROWS * DIM];
__device__ float  g_sim[(size_t)BATCH * SEQ * SEQ];
__device__ float2 g_stats[(size_t)MROWS];

// ---------------------------------------------------------------------------
// Helpers
// ---------------------------------------------------------------------------
__device__ __forceinline__ void split2(float a, float b, unsigned &h, unsigned &l) {
    __half2 hh = __floats2half2_rn(a, b);
    float2 r = __half22float2(hh);
    __half2 ll = __floats2half2_rn(a - r.x, b - r.y);
    h = *(unsigned*)&hh;
    l = *(unsigned*)&ll;
}

__device__ __forceinline__ void cpa16(unsigned dst, const void* src) {
    asm volatile("cp.async.cg.shared.global [%0], [%1], 16;"
                 :: "r"(dst), "l"(src) : "memory");
}
__device__ __forceinline__ void cpa_commit() {
    asm volatile("cp.async.commit_group;" ::: "memory");
}
__device__ __forceinline__ void cpa_wait1() {
    asm volatile("cp.async.wait_group 1;" ::: "memory");
}
__device__ __forceinline__ void cpa_wait0() {
    asm volatile("cp.async.wait_group 0;" ::: "memory");
}

#define MMA_F16(ACC, A0, A1, A2, A3, B0, B1)                                  \
    asm volatile(                                                             \
        "mma.sync.aligned.m16n8k16.row.col.f32.f16.f16.f32 "                 \
        "{%0,%1,%2,%3}, {%4,%5,%6,%7}, {%8,%9}, {%0,%1,%2,%3};"              \
        : "+f"(ACC[0]), "+f"(ACC[1]), "+f"(ACC[2]), "+f"(ACC[3])             \
        : "r"(A0), "r"(A1), "r"(A2), "r"(A3), "r"(B0), "r"(B1))

#define LDM_X4(R0, R1, R2, R3, ADDR)                                          \
    asm volatile("ldmatrix.sync.aligned.m8n8.x4.shared.b16 {%0,%1,%2,%3}, [%4];" \
        : "=r"(R0), "=r"(R1), "=r"(R2), "=r"(R3) : "r"(ADDR))

// ---------------------------------------------------------------------------
// Shared compute tile: 2 k-steps. PX selects precision scheme.
// ---------------------------------------------------------------------------
template <int PX>
__device__ __forceinline__ void compute_tile(unsigned stb, unsigned aoff,
                                             unsigned boff, float acc[4][4][4])
{
    #pragma unroll
    for (int ks = 0; ks < 2; ks++) {
        const unsigned kb = ks * 32;   // 16 halves = 32 bytes

        unsigned afH[4][4], afL[4][4];
        #pragma unroll
        for (int mt = 0; mt < 4; mt++) {
            const unsigned ah = stb + O_AH + aoff + mt * (16 * SROW * 2) + kb;
            LDM_X4(afH[mt][0], afH[mt][1], afH[mt][2], afH[mt][3], ah);
            if (PX == PX_X3) {
                const unsigned al = stb + O_AL + aoff + mt * (16 * SROW * 2) + kb;
                LDM_X4(afL[mt][0], afL[mt][1], afL[mt][2], afL[mt][3], al);
            }
        }
        unsigned bfH[4][2], bfL[4][2];
        #pragma unroll
        for (int p = 0; p < 2; p++) {
            const unsigned bh = stb + O_BH + boff + p * (16 * SROW * 2) + kb;
            LDM_X4(bfH[2*p][0], bfH[2*p][1], bfH[2*p+1][0], bfH[2*p+1][1], bh);
            if (PX == PX_X3 || PX == PX_BL) {
                const unsigned bl = stb + O_BL + boff + p * (16 * SROW * 2) + kb;
                LDM_X4(bfL[2*p][0], bfL[2*p][1], bfL[2*p+1][0], bfL[2*p+1][1], bl);
            }
        }
        #pragma unroll
        for (int mt = 0; mt < 4; mt++)
            #pragma unroll
            for (int nt = 0; nt < 4; nt++) {
                float* a4 = acc[mt][nt];
                if (PX == PX_X3) {
                    MMA_F16(a4, afL[mt][0], afL[mt][1], afL[mt][2], afL[mt][3],
                            bfH[nt][0], bfH[nt][1]);
                }
                if (PX == PX_X3 || PX == PX_BL) {
                    MMA_F16(a4, afH[mt][0], afH[mt][1], afH[mt][2], afH[mt][3],
                            bfL[nt][0], bfL[nt][1]);
                }
                MMA_F16(a4, afH[mt][0], afH[mt][1], afH[mt][2], afH[mt][3],
                        bfH[nt][0], bfH[nt][1]);
            }
    }
}

// Per-thread ldmatrix offsets.
__device__ __forceinline__ void frag_offsets(int warp, int lane,
                                             unsigned &aoff, unsigned &boff)
{
    const int wm = warp >> 2, wn = warp & 3;
    const int t8 = lane >> 3, r8 = lane & 7;
    aoff = ((wm * 64 + ((t8 & 1) << 3) + r8) * SROW + ((t8 >> 1) << 3)) * 2;
    boff = ((wn * 32 + ((t8 >> 1) << 3) + r8) * SROW + ((t8 & 1) << 3)) * 2;
}

// ---------------------------------------------------------------------------
// NT GEMM with cp.async pipeline. X3: 1 -> fp16x3, 0 -> hi-only.
// C[M,N] = alpha * A[M,K(ldA)] * (B[N,K(ldB)])^T + bias
// mode 0: write fp32 C (ldC).  mode 1: write split half oH/oL (ldC);
//         lo written only for columns >= loMinCol.
// ---------------------------------------------------------------------------
template <int X3>
__global__ __launch_bounds__(NTH, 1)
void gemm_f16(const __half* __restrict__ aHg, const __half* __restrict__ aLg,
              const __half* __restrict__ bHg, const __half* __restrict__ bLg,
              const float* __restrict__ bias, float* __restrict__ C,
              __half* __restrict__ oH, __half* __restrict__ oL,
              int M, int N, int K, int ldA, int ldB, int ldC,
              float alpha, int mode, int loMinCol,
              long sA, long sB, long sC)
{
    extern __shared__ __align__(16) char dyn[];

    const long zb = blockIdx.z;
    aHg += zb * sA; if (X3) aLg += zb * sA;
    bHg += zb * sB; if (X3) bLg += zb * sB;
    if (C)  C  += zb * sC;
    if (oH) { oH += zb * sC; oL += zb * sC; }

    const int tid  = threadIdx.x;
    const int row0 = blockIdx.y * BM;
    const int col0 = blockIdx.x * BN;

    const int warp = tid >> 5;
    const int lane = tid & 31;
    const int wm   = warp >> 2;
    const int wn   = warp & 3;
    const int g    = lane >> 2;
    const int t4   = lane & 3;

    const unsigned sb = (unsigned)__cvta_generic_to_shared(dyn);
    unsigned aoff, boff;
    frag_offsets(warp, lane, aoff, boff);

    const int arow0 = tid >> 2;
    const int apart = (tid & 3) * 8;
    const __half* srcAH0 = aHg + (long)(row0 + arow0) * ldA + apart;
    const __half* srcAH1 = aHg + (long)(row0 + 128 + arow0) * ldA + apart;
    const __half* srcAL0 = X3 ? (aLg + (long)(row0 + arow0) * ldA + apart) : srcAH0;
    const __half* srcAL1 = X3 ? (aLg + (long)(row0 + 128 + arow0) * ldA + apart) : srcAH1;
    const __half* srcBH  = bHg + (long)(col0 + arow0) * ldB + apart;
    const __half* srcBL  = X3 ? (bLg + (long)(col0 + arow0) * ldB + apart) : srcBH;
    const unsigned dA0 = arow0 * (SROW * 2) + apart * 2;
    const unsigned dA1 = (128 + arow0) * (SROW * 2) + apart * 2;
    const unsigned dB  = arow0 * (SROW * 2) + apart * 2;

    const int NIT = K / BK;

#define ISSUE(STG, IT)                                                        \
    {                                                                         \
        const long ko = (long)(IT) * BK;                                      \
        const unsigned st = sb + (STG) * STAGE_BYTES;                         \
        cpa16(st + O_AH + dA0, srcAH0 + ko);                                  \
        cpa16(st + O_AH + dA1, srcAH1 + ko);                                  \
        cpa16(st + O_BH + dB,  srcBH  + ko);                                  \
        if (X3) {                                                             \
            cpa16(st + O_AL + dA0, srcAL0 + ko);                              \
            cpa16(st + O_AL + dA1, srcAL1 + ko);                              \
            cpa16(st + O_BL + dB,  srcBL  + ko);                              \
        }                                                                     \
        cpa_commit();                                                         \
    }

    float acc[4][4][4] = {};

    ISSUE(0, 0);
    ISSUE(1, 1);

    int cur = 0;
    for (int it = 0; it < NIT; it++) {
        if (it + 1 < NIT) cpa_wait1(); else cpa_wait0();
        __syncthreads();

        compute_tile<X3 ? PX_X3 : PX_HI>(sb + cur * STAGE_BYTES, aoff, boff, acc);

        if (it + 2 < NIT) ISSUE((cur + 2) % NSTAGES, it + 2);
        if (++cur == NSTAGES) cur = 0;
    }
#undef ISSUE

    // ---- epilogue ----
    const bool wantLo = (col0 + BN > loMinCol);
    #pragma unroll
    for (int mt = 0; mt < 4; mt++) {
        const int r = row0 + wm * 64 + mt * 16 + g;
        #pragma unroll
        for (int nt = 0; nt < 4; nt++) {
            const int c = col0 + wn * 32 + nt * 8 + 2 * t4;
            float b0 = 0.f, b1 = 0.f;
            if (bias) { b0 = bias[c]; b1 = bias[c + 1]; }
            float2 v0, v1;
            v0.x = alpha * acc[mt][nt][0] + b0;
            v0.y = alpha * acc[mt][nt][1] + b1;
            v1.x = alpha * acc[mt][nt][2] + b0;
            v1.y = alpha * acc[mt][nt][3] + b1;
            if (mode == 0) {
                *(float2*)(C + (long)r * ldC + c)       = v0;
                *(float2*)(C + (long)(r + 8) * ldC + c) = v1;
            } else {
                unsigned h, l;
                split2(v0.x, v0.y, h, l);
                *(unsigned*)(oH + (long)r * ldC + c) = h;
                if (wantLo) *(unsigned*)(oL + (long)r * ldC + c) = l;
                split2(v1.x, v1.y, h, l);
                *(unsigned*)(oH + (long)(r + 8) * ldC + c) = h;
                if (wantLo) *(unsigned*)(oL + (long)(r + 8) * ldC + c) = l;
            }
        }
    }
}

// ---------------------------------------------------------------------------
// Fused attn@V GEMM: A = softmax(sim) on the fly (hi only); B = Vt split.
// Precision PX_BL: pH*vL + pH*vH.
// ---------------------------------------------------------------------------
__global__ __launch_bounds__(NTH, 1)
void gemm_av(const float* __restrict__ sim, const float2* __restrict__ stats,
             const __half* __restrict__ bHg, const __half* __restrict__ bLg,
             float* __restrict__ C, int N, int K,
             long sA, long sB, long sC)
{
    extern __shared__ __align__(16) char dyn[];

    const long zb = blockIdx.z;
    sim += zb * sA;
    bHg += zb * sB; bLg += zb * sB;
    C   += zb * sC;

    const int tid  = threadIdx.x;
    const int row0 = blockIdx.y * BM;
    const int col0 = blockIdx.x * BN;

    const int warp = tid >> 5;
    const int lane = tid & 31;
    const int wm   = warp >> 2;
    const int wn   = warp & 3;
    const int g    = lane >> 2;
    const int t4   = lane & 3;

    const unsigned sb = (unsigned)__cvta_generic_to_shared(dyn);
    unsigned aoff, boff;
    frag_offsets(warp, lane, aoff, boff);

    const int arow = tid >> 1;
    const int ak0  = (tid & 1) * 16;
    const float* srcA = sim + (long)(row0 + arow) * K + ak0;
    const float2 st = stats[zb * SEQ + row0 + arow];
    const float mx = st.x, inv = st.y;
    const unsigned dA = arow * (SROW * 2) + ak0 * 2;

    const int brow = tid >> 2;
    const int bpart = (tid & 3) * 8;
    const __half* srcBH = bHg + (long)(col0 + brow) * K + bpart;
    const __half* srcBL = bLg + (long)(col0 + brow) * K + bpart;
    const unsigned dB = brow * (SROW * 2) + bpart * 2;

    const int NIT = K / BK;
    float4 aReg[4];

#define LOADA(IT)                                                             \
    {                                                                         \
        const long ko = (long)(IT) * BK;                                      \
        _Pragma("unroll")                                                     \
        for (int i = 0; i < 4; i++)                                           \
            aReg[i] = *(const float4*)(srcA + ko + 4 * i);                    \
    }
#define STSA(STG)                                                             \
    {                                                                         \
        char* st_ = dyn + (STG) * STAGE_BYTES;                                \
        _Pragma("unroll")                                                     \
        for (int i = 0; i < 4; i++) {                                         \
            float p0 = __expf(aReg[i].x - mx) * inv;                          \
            float p1 = __expf(aReg[i].y - mx) * inv;                          \
            float p2 = __expf(aReg[i].z - mx) * inv;                          \
            float p3 = __expf(aReg[i].w - mx) * inv;                          \
            __half2 h0 = __floats2half2_rn(p0, p1);                           \
            __half2 h1 = __floats2half2_rn(p2, p3);                           \
            uint2 hh;                                                         \
            hh.x = *(unsigned*)&h0;                                           \
            hh.y = *(unsigned*)&h1;                                           \
            *(uint2*)(st_ + O_AH + dA + 8 * i) = hh;                          \
        }                                                                     \
    }
#define ISSUEB(STG, IT)                                                       \
    {                                                                         \
        const long ko = (long)(IT) * BK;                                      \
        const unsigned st = sb + (STG) * STAGE_BYTES;                         \
        cpa16(st + O_BH + dB, srcBH + ko);                                    \
        cpa16(st + O_BL + dB, srcBL + ko);                                    \
        cpa_commit();                                                         \
    }

    float acc[4][4][4] = {};

    LOADA(0); STSA(0);
    LOADA(1); STSA(1);
    ISSUEB(0, 0);
    ISSUEB(1, 1);

    int cur = 0;
    for (int it = 0; it < NIT; it++) {
        if (it + 1 < NIT) cpa_wait1(); else cpa_wait0();
        __syncthreads();

        if (it + 2 < NIT) LOADA(it + 2);

        compute_tile<PX_BL>(sb + cur * STAGE_BYTES, aoff, boff, acc);

        if (it + 2 < NIT) {
            STSA((cur + 2) % NSTAGES);
            ISSUEB((cur + 2) % NSTAGES, it + 2);
        }
        if (++cur == NSTAGES) cur = 0;
    }
#undef LOADA
#undef STSA
#undef ISSUEB

    #pragma unroll
    for (int mt = 0; mt < 4; mt++) {
        const int r = row0 + wm * 64 + mt * 16 + g;
        #pragma unroll
        for (int nt = 0; nt < 4; nt++) {
            const int c = col0 + wn * 32 + nt * 8 + 2 * t4;
            float2 v0, v1;
            v0.x = acc[mt][nt][0];
            v0.y = acc[mt][nt][1];
            v1.x = acc[mt][nt][2];
            v1.y = acc[mt][nt][3];
            *(float2*)(C + (long)r * N + c)       = v0;
            *(float2*)(C + (long)(r + 8) * N + c) = v1;
        }
    }
}

// ---------------------------------------------------------------------------
// Row stats: max + 1/sum(exp) over SEQ cols. One block per row.
// ---------------------------------------------------------------------------
__global__ __launch_bounds__(256)
void rowstat(const float* __restrict__ sim, float2* __restrict__ stats)
{
    const float* p = sim + (long)blockIdx.x * SEQ;
    const int tid = threadIdx.x;

    float v[8];
    float mx = -1e30f;
    #pragma unroll
    for (int i = 0; i < 8; i++) {
        v[i] = p[tid + i * 256];
        mx = fmaxf(mx, v[i]);
    }
    #pragma unroll
    for (int o = 16; o; o >>= 1)
        mx = fmaxf(mx, __shfl_xor_sync(0xffffffffu, mx, o));
    __shared__ float red[8];
    if ((tid & 31) == 0) red[tid >> 5] = mx;
    __syncthreads();
    mx = red[0];
    #pragma unroll
    for (int w = 1; w < 8; w++) mx = fmaxf(mx, red[w]);

    float s = 0.f;
    #pragma unroll
    for (int i = 0; i < 8; i++)
        s += __expf(v[i] - mx);
    #pragma unroll
    for (int o = 16; o; o >>= 1)
        s += __shfl_xor_sync(0xffffffffu, s, o);
    __syncthreads();
    if ((tid & 31) == 0) red[tid >> 5] = s;
    __syncthreads();
    s = red[0];
    #pragma unroll
    for (int w = 1; w < 8; w++) s += red[w];

    if (tid == 0) {
        float2 st;
        st.x = mx;
        st.y = 1.0f / s;
        stats[blockIdx.x] = st;
    }
}

// ---------------------------------------------------------------------------
// Elementwise split: fp32 -> half hi/lo
// ---------------------------------------------------------------------------
__global__ __launch_bounds__(256)
void split_hl(const float* __restrict__ in, __half* __restrict__ oH,
              __half* __restrict__ oL, long n4)
{
    const long i = (long)blockIdx.x * 256 + threadIdx.x;
    if (i >= n4) return;
    float4 v = *(const float4*)(in + 4 * i);
    uint2 hh, ll;
    split2(v.x, v.y, hh.x, ll.x);
    split2(v.z, v.w, hh.y, ll.y);
    *(uint2*)(oH + 4 * i) = hh;
    *(uint2*)(oL + 4 * i) = ll;
}

// ---------------------------------------------------------------------------
// Transpose + split: in[R,C] fp32 -> oH/oL[C,R] half (square 512x512 weights).
// ---------------------------------------------------------------------------
__global__ __launch_bounds__(256)
void transpose_split(const float* __restrict__ in,
                     __half* __restrict__ oH, __half* __restrict__ oL,
                     int R, int C)
{
    __shared__ float t[32][33];
    const int tx = threadIdx.x & 31;
    const int ty = threadIdx.x >> 5;
    const int bx = blockIdx.x * 32;
    const int by = blockIdx.y * 32;
    #pragma unroll
    for (int jj = 0; jj < 4; jj++)
        t[ty + 8 * jj][tx] = in[(long)(by + ty + 8 * jj) * C + bx + tx];
    __syncthreads();
    #pragma unroll
    for (int jj = 0; jj < 4; jj++) {
        const float f = t[tx][ty + 8 * jj];
        const __half h = __float2half_rn(f);
        const __half l = __float2half_rn(f - __half2float(h));
        const long o = (long)(bx + ty + 8 * jj) * R + by + tx;
        oH[o] = h;
        oL[o] = l;
    }
}

// ---------------------------------------------------------------------------
// V transpose from strided qkv split layout: vt[b][d][s] = v[b][s][d]
// ---------------------------------------------------------------------------
__global__ __launch_bounds__(256)
void transpose_v(const __half* __restrict__ qkvH, const __half* __restrict__ qkvL,
                 __half* __restrict__ vtH, __half* __restrict__ vtL)
{
    __shared__ float t[32][33];
    const long inB  = (long)blockIdx.z * SEQ * NQKV;
    const long outB = (long)blockIdx.z * SEQ * DIM;
    const int tx = threadIdx.x & 31;
    const int ty = threadIdx.x >> 5;
    const int bx = blockIdx.x * 32;   // d base
    const int by = blockIdx.y * 32;   // s base
    #pragma unroll
    for (int jj = 0; jj < 4; jj++) {
        const long idx = inB + (long)(by + ty + 8 * jj) * NQKV + 1024 + bx + tx;
        t[ty + 8 * jj][tx] = __half2float(qkvH[idx]) + __half2float(qkvL[idx]);
    }
    __syncthreads();
    #pragma unroll
    for (int jj = 0; jj < 4; jj++) {
        const float f = t[tx][ty + 8 * jj];
        const __half h = __float2half_rn(f);
        const __half l = __float2half_rn(f - __half2float(h));
        const long o = outB + (long)(bx + ty + 8 * jj) * SEQ + by + tx;
        vtH[o] = h;
        vtL[o] = l;
    }
}

// ---------------------------------------------------------------------------
// Bias concat: [bq | bk | bv] -> g_bias[1536]
// ---------------------------------------------------------------------------
__global__ __launch_bounds__(256)
void concat_bias(const float* __restrict__ bq, const float* __restrict__ bk,
                 const float* __restrict__ bv, float* __restrict__ b)
{
    const int i = blockIdx.x * 256 + threadIdx.x;
    if (i < 512)       b[i] = bq[i];
    else if (i < 1024) b[i] = bk[i - 512];
    else if (i < 1536) b[i] = bv[i - 1024];
}

// ---------------------------------------------------------------------------
// Launch
// ---------------------------------------------------------------------------
extern "C" void kernel_launch(void* const* d_in, const int* in_sizes, int n_in,
                              void* d_out, int out_size)
{
    const float* x  = (const float*)d_in[0];
    const float* Wq = (const float*)d_in[1];
    const float* bq = (const float*)d_in[2];
    const float* Wk = (const float*)d_in[3];
    const float* bk = (const float*)d_in[4];
    const float* Wv = (const float*)d_in[5];
    const float* bv = (const float*)d_in[6];
    float* out = (float*)d_out;

    __half *xH, *xL, *wH, *wL, *qkvH, *qkvL, *vtH, *vtL;
    float *sim, *bias;
    float2* stats;
    cudaGetSymbolAddress((void**)&xH, g_xH);
    cudaGetSymbolAddress((void**)&xL, g_xL);
    cudaGetSymbolAddress((void**)&wH, g_wH);
    cudaGetSymbolAddress((void**)&wL, g_wL);
    cudaGetSymbolAddress((void**)&bias, g_bias);
    cudaGetSymbolAddress((void**)&qkvH, g_qkvH);
    cudaGetSymbolAddress((void**)&qkvL, g_qkvL);
    cudaGetSymbolAddress((void**)&vtH, g_vtH);
    cudaGetSymbolAddress((void**)&vtL, g_vtL);
    cudaGetSymbolAddress((void**)&sim, g_sim);
    cudaGetSymbolAddress((void**)&stats, g_stats);

    cudaFuncSetAttribute(gemm_f16<1>,
                         cudaFuncAttributeMaxDynamicSharedMemorySize, SMEM_BYTES);
    cudaFuncSetAttribute(gemm_f16<0>,
                         cudaFuncAttributeMaxDynamicSharedMemorySize, SMEM_BYTES);
    cudaFuncSetAttribute(gemm_av,
                         cudaFuncAttributeMaxDynamicSharedMemorySize, SMEM_BYTES);

    // 0a) split x into half hi/lo
    {
        const long n4 = (long)MROWS * DIM / 4;
        split_hl<<<(unsigned)((n4 + 255) / 256), 256>>>(x, xH, xL, n4);
    }
    // 0b) transpose+split each weight into its [512,512] slab of [1536,512]
    {
        dim3 grid(DIM / 32, DIM / 32, 1);
        transpose_split<<<grid, 256>>>(Wq, wH, wL, DIM, DIM);
        transpose_split<<<grid, 256>>>(Wk, wH + (size_t)DIM * DIM,
                                       wL + (size_t)DIM * DIM, DIM, DIM);
        transpose_split<<<grid, 256>>>(Wv, wH + 2 * (size_t)DIM * DIM,
                                       wL + 2 * (size_t)DIM * DIM, DIM, DIM);
    }
    // 0c) bias concat
    concat_bias<<<6, 256>>>(bq, bk, bv, bias);

    // 1) Fused QKV projection: [32768,1536] = x @ [Wq|Wk|Wv]^T + bias.
    //    lo written only for V columns (>= 1024); Q/K lo is never consumed.
    {
        dim3 grid(NQKV / BN, MROWS / BM, 1);
        gemm_f16<1><<<grid, NTH, SMEM_BYTES>>>(xH, xL, wH, wL, bias,
                                               nullptr, qkvH, qkvL,
                                               MROWS, NQKV, DIM,
                                               DIM, DIM, NQKV,
                                               1.0f, 1, 1024, 0, 0, 0);
    }

    // 1b) transpose V slab -> vtH/vtL [b][d][s]
    {
        dim3 grid(DIM / 32, SEQ / 32, BATCH);
        transpose_v<<<grid, 256>>>(qkvH, qkvL, vtH, vtL);
    }

    // 2) sim[b] = Q[b] @ K[b]^T * SCALE (fp16 x1, hi parts only) -> fp32
    {
        dim3 grid(SEQ / BN, SEQ / BM, BATCH);
        gemm_f16<0><<<grid, NTH, SMEM_BYTES>>>(qkvH, nullptr,
                                               qkvH + 512, nullptr, nullptr,
                                               sim, nullptr, nullptr,
                                               SEQ, SEQ, DIM,
                                               NQKV, NQKV, SEQ,
                                               SCALE, 0, NQKV,
                                               (long)SEQ * NQKV,
                                               (long)SEQ * NQKV,
                                               (long)SEQ * SEQ);
    }

    // 3) row stats (max, 1/sum)
    rowstat<<<MROWS, 256>>>(sim, stats);

    // 4) out[b] = softmax(sim[b]) @ Vt[b]^T (x2: pH*vH + pH*vL)
    {
        dim3 grid(DIM / BN, SEQ / BM, BATCH);
        gemm_av<<<grid, NTH, SMEM_BYTES>>>(sim, stats, vtH, vtL, out,
                                           DIM, SEQ,
                                           (long)SEQ * SEQ, (long)DIM * SEQ,
                                           (long)SEQ * DIM);
    }
}

// round 15
// speedup vs baseline: 1.4880x; 1.4880x over previous
#include <cuda_runtime.h>
#include <cuda_fp16.h>
#include <cstdint>
#include <math.h>

// Problem constants
#define BATCH 16
#define SEQ   2048
#define DIM   512
#define NQKV  1536
#define MROWS (BATCH * SEQ)   // 32768
#define SCALE 0.125f

// GEMM tile config: CTA 256x128, BK=32, 512 threads (16 warps, 4x4), warp 64x32
#define BM 256
#define BN 128
#define BK 32
#define NTH 512

#define SROW 40                      // halves per row (32 + 8 pad)
#define O_AH 0
#define O_AL (BM * SROW * 2)         // 20480
#define O_BH (2 * BM * SROW * 2)     // 40960
#define O_BL (O_BH + BN * SROW * 2)  // 51200
#define STAGE_BYTES (O_BL + BN * SROW * 2)   // 61440
#define NSTAGES 3
#define SMEM_BYTES (NSTAGES * STAGE_BYTES)   // 184320

// Precision schemes for compute_tile
#define PX_HI  0   // aH*bH only
#define PX_X3  1   // aL*bH + aH*bL + aH*bH
#define PX_BL  2   // aH*bL + aH*bH  (no A-lo)

// ---------------------------------------------------------------------------
// Scratch (device globals — no allocation allowed)
// ---------------------------------------------------------------------------
__device__ __half g_xH[(size_t)MROWS * DIM];
__device__ __half g_xL[(size_t)MROWS * DIM];
__device__ __half g_wH[(size_t)NQKV * DIM];
__device__ __half g_wL[(size_t)NQKV * DIM];
__device__ float  g_bias[NQKV];
__device__ __half g_qkvH[(size_t)MROWS * NQKV];
__device__ __half g_qkvL[(size_t)MROWS * NQKV];
__device__ __half g_vtH[(size_t)MROWS * DIM];
__device__ __half g_vtL[(size_t)MROWS * DIM];
__device__ float  g_sim[(size_t)BATCH * SEQ * SEQ];
__device__ float2 g_stats[(size_t)MROWS];

// ---------------------------------------------------------------------------
// Helpers
// ---------------------------------------------------------------------------
__device__ __forceinline__ void split2(float a, float b, unsigned &h, unsigned &l) {
    __half2 hh = __floats2half2_rn(a, b);
    float2 r = __half22float2(hh);
    __half2 ll = __floats2half2_rn(a - r.x, b - r.y);
    h = *(unsigned*)&hh;
    l = *(unsigned*)&ll;
}

__device__ __forceinline__ void cpa16(unsigned dst, const void* src) {
    asm volatile("cp.async.cg.shared.global [%0], [%1], 16;"
                 :: "r"(dst), "l"(src) : "memory");
}
__device__ __forceinline__ void cpa_commit() {
    asm volatile("cp.async.commit_group;" ::: "memory");
}
__device__ __forceinline__ void cpa_wait1() {
    asm volatile("cp.async.wait_group 1;" ::: "memory");
}
__device__ __forceinline__ void cpa_wait0() {
    asm volatile("cp.async.wait_group 0;" ::: "memory");
}

#define MMA_F16(ACC, A0, A1, A2, A3, B0, B1)                                  \
    asm volatile(                                                             \
        "mma.sync.aligned.m16n8k16.row.col.f32.f16.f16.f32 "                 \
        "{%0,%1,%2,%3}, {%4,%5,%6,%7}, {%8,%9}, {%0,%1,%2,%3};"              \
        : "+f"(ACC[0]), "+f"(ACC[1]), "+f"(ACC[2]), "+f"(ACC[3])             \
        : "r"(A0), "r"(A1), "r"(A2), "r"(A3), "r"(B0), "r"(B1))

#define LDM_X4(R0, R1, R2, R3, ADDR)                                          \
    asm volatile("ldmatrix.sync.aligned.m8n8.x4.shared.b16 {%0,%1,%2,%3}, [%4];" \
        : "=r"(R0), "=r"(R1), "=r"(R2), "=r"(R3) : "r"(ADDR))

// ---------------------------------------------------------------------------
// Shared compute tile: 2 k-steps. PX selects precision scheme.
// ---------------------------------------------------------------------------
template <int PX>
__device__ __forceinline__ void compute_tile(unsigned stb, unsigned aoff,
                                             unsigned boff, float acc[4][4][4])
{
    #pragma unroll
    for (int ks = 0; ks < 2; ks++) {
        const unsigned kb = ks * 32;   // 16 halves = 32 bytes

        unsigned afH[4][4], afL[4][4];
        #pragma unroll
        for (int mt = 0; mt < 4; mt++) {
            const unsigned ah = stb + O_AH + aoff + mt * (16 * SROW * 2) + kb;
            LDM_X4(afH[mt][0], afH[mt][1], afH[mt][2], afH[mt][3], ah);
            if (PX == PX_X3) {
                const unsigned al = stb + O_AL + aoff + mt * (16 * SROW * 2) + kb;
                LDM_X4(afL[mt][0], afL[mt][1], afL[mt][2], afL[mt][3], al);
            }
        }
        unsigned bfH[4][2], bfL[4][2];
        #pragma unroll
        for (int p = 0; p < 2; p++) {
            const unsigned bh = stb + O_BH + boff + p * (16 * SROW * 2) + kb;
            LDM_X4(bfH[2*p][0], bfH[2*p][1], bfH[2*p+1][0], bfH[2*p+1][1], bh);
            if (PX == PX_X3 || PX == PX_BL) {
                const unsigned bl = stb + O_BL + boff + p * (16 * SROW * 2) + kb;
                LDM_X4(bfL[2*p][0], bfL[2*p][1], bfL[2*p+1][0], bfL[2*p+1][1], bl);
            }
        }
        #pragma unroll
        for (int mt = 0; mt < 4; mt++)
            #pragma unroll
            for (int nt = 0; nt < 4; nt++) {
                float* a4 = acc[mt][nt];
                if (PX == PX_X3) {
                    MMA_F16(a4, afL[mt][0], afL[mt][1], afL[mt][2], afL[mt][3],
                            bfH[nt][0], bfH[nt][1]);
                }
                if (PX == PX_X3 || PX == PX_BL) {
                    MMA_F16(a4, afH[mt][0], afH[mt][1], afH[mt][2], afH[mt][3],
                            bfL[nt][0], bfL[nt][1]);
                }
                MMA_F16(a4, afH[mt][0], afH[mt][1], afH[mt][2], afH[mt][3],
                        bfH[nt][0], bfH[nt][1]);
            }
    }
}

// Per-thread ldmatrix offsets.
__device__ __forceinline__ void frag_offsets(int warp, int lane,
                                             unsigned &aoff, unsigned &boff)
{
    const int wm = warp >> 2, wn = warp & 3;
    const int t8 = lane >> 3, r8 = lane & 7;
    aoff = ((wm * 64 + ((t8 & 1) << 3) + r8) * SROW + ((t8 >> 1) << 3)) * 2;
    boff = ((wn * 32 + ((t8 >> 1) << 3) + r8) * SROW + ((t8 & 1) << 3)) * 2;
}

// ---------------------------------------------------------------------------
// NT GEMM with cp.async pipeline. X3: 1 -> fp16x3, 0 -> hi-only.
// C[M,N] = alpha * A[M,K(ldA)] * (B[N,K(ldB)])^T + bias
// mode 0: write fp32 C (ldC).  mode 1: write split half oH/oL (ldC);
//         lo written only for columns >= loMinCol.
// ---------------------------------------------------------------------------
template <int X3>
__global__ __launch_bounds__(NTH, 1)
void gemm_f16(const __half* __restrict__ aHg, const __half* __restrict__ aLg,
              const __half* __restrict__ bHg, const __half* __restrict__ bLg,
              const float* __restrict__ bias, float* __restrict__ C,
              __half* __restrict__ oH, __half* __restrict__ oL,
              int M, int N, int K, int ldA, int ldB, int ldC,
              float alpha, int mode, int loMinCol,
              long sA, long sB, long sC)
{
    extern __shared__ __align__(16) char dyn[];

    const long zb = blockIdx.z;
    aHg += zb * sA; if (X3) aLg += zb * sA;
    bHg += zb * sB; if (X3) bLg += zb * sB;
    if (C)  C  += zb * sC;
    if (oH) { oH += zb * sC; oL += zb * sC; }

    const int tid  = threadIdx.x;
    const int row0 = blockIdx.y * BM;
    const int col0 = blockIdx.x * BN;

    const int warp = tid >> 5;
    const int lane = tid & 31;
    const int wm   = warp >> 2;
    const int wn   = warp & 3;
    const int g    = lane >> 2;
    const int t4   = lane & 3;

    const unsigned sb = (unsigned)__cvta_generic_to_shared(dyn);
    unsigned aoff, boff;
    frag_offsets(warp, lane, aoff, boff);

    const int arow0 = tid >> 2;
    const int apart = (tid & 3) * 8;
    const __half* srcAH0 = aHg + (long)(row0 + arow0) * ldA + apart;
    const __half* srcAH1 = aHg + (long)(row0 + 128 + arow0) * ldA + apart;
    const __half* srcAL0 = X3 ? (aLg + (long)(row0 + arow0) * ldA + apart) : srcAH0;
    const __half* srcAL1 = X3 ? (aLg + (long)(row0 + 128 + arow0) * ldA + apart) : srcAH1;
    const __half* srcBH  = bHg + (long)(col0 + arow0) * ldB + apart;
    const __half* srcBL  = X3 ? (bLg + (long)(col0 + arow0) * ldB + apart) : srcBH;
    const unsigned dA0 = arow0 * (SROW * 2) + apart * 2;
    const unsigned dA1 = (128 + arow0) * (SROW * 2) + apart * 2;
    const unsigned dB  = arow0 * (SROW * 2) + apart * 2;

    const int NIT = K / BK;

#define ISSUE(STG, IT)                                                        \
    {                                                                         \
        const long ko = (long)(IT) * BK;                                      \
        const unsigned st = sb + (STG) * STAGE_BYTES;                         \
        cpa16(st + O_AH + dA0, srcAH0 + ko);                                  \
        cpa16(st + O_AH + dA1, srcAH1 + ko);                                  \
        cpa16(st + O_BH + dB,  srcBH  + ko);                                  \
        if (X3) {                                                             \
            cpa16(st + O_AL + dA0, srcAL0 + ko);                              \
            cpa16(st + O_AL + dA1, srcAL1 + ko);                              \
            cpa16(st + O_BL + dB,  srcBL  + ko);                              \
        }                                                                     \
        cpa_commit();                                                         \
    }

    float acc[4][4][4] = {};

    ISSUE(0, 0);
    ISSUE(1, 1);

    int cur = 0;
    for (int it = 0; it < NIT; it++) {
        if (it + 1 < NIT) cpa_wait1(); else cpa_wait0();
        __syncthreads();

        compute_tile<X3 ? PX_X3 : PX_HI>(sb + cur * STAGE_BYTES, aoff, boff, acc);

        if (it + 2 < NIT) ISSUE((cur + 2) % NSTAGES, it + 2);
        if (++cur == NSTAGES) cur = 0;
    }
#undef ISSUE

    // ---- epilogue ----
    const bool wantLo = (col0 + BN > loMinCol);
    #pragma unroll
    for (int mt = 0; mt < 4; mt++) {
        const int r = row0 + wm * 64 + mt * 16 + g;
        #pragma unroll
        for (int nt = 0; nt < 4; nt++) {
            const int c = col0 + wn * 32 + nt * 8 + 2 * t4;
            float b0 = 0.f, b1 = 0.f;
            if (bias) { b0 = bias[c]; b1 = bias[c + 1]; }
            float2 v0, v1;
            v0.x = alpha * acc[mt][nt][0] + b0;
            v0.y = alpha * acc[mt][nt][1] + b1;
            v1.x = alpha * acc[mt][nt][2] + b0;
            v1.y = alpha * acc[mt][nt][3] + b1;
            if (mode == 0) {
                *(float2*)(C + (long)r * ldC + c)       = v0;
                *(float2*)(C + (long)(r + 8) * ldC + c) = v1;
            } else {
                unsigned h, l;
                split2(v0.x, v0.y, h, l);
                *(unsigned*)(oH + (long)r * ldC + c) = h;
                if (wantLo) *(unsigned*)(oL + (long)r * ldC + c) = l;
                split2(v1.x, v1.y, h, l);
                *(unsigned*)(oH + (long)(r + 8) * ldC + c) = h;
                if (wantLo) *(unsigned*)(oL + (long)(r + 8) * ldC + c) = l;
            }
        }
    }
}

// ---------------------------------------------------------------------------
// Fused attn@V GEMM: A = softmax(sim) on the fly (hi only); B = Vt split.
// Precision PX_BL: pH*vL + pH*vH.
// ---------------------------------------------------------------------------
__global__ __launch_bounds__(NTH, 1)
void gemm_av(const float* __restrict__ sim, const float2* __restrict__ stats,
             const __half* __restrict__ bHg, const __half* __restrict__ bLg,
             float* __restrict__ C, int N, int K,
             long sA, long sB, long sC)
{
    extern __shared__ __align__(16) char dyn[];

    const long zb = blockIdx.z;
    sim += zb * sA;
    bHg += zb * sB; bLg += zb * sB;
    C   += zb * sC;

    const int tid  = threadIdx.x;
    const int row0 = blockIdx.y * BM;
    const int col0 = blockIdx.x * BN;

    const int warp = tid >> 5;
    const int lane = tid & 31;
    const int wm   = warp >> 2;
    const int wn   = warp & 3;
    const int g    = lane >> 2;
    const int t4   = lane & 3;

    const unsigned sb = (unsigned)__cvta_generic_to_shared(dyn);
    unsigned aoff, boff;
    frag_offsets(warp, lane, aoff, boff);

    const int arow = tid >> 1;
    const int ak0  = (tid & 1) * 16;
    const float* srcA = sim + (long)(row0 + arow) * K + ak0;
    const float2 st = stats[zb * SEQ + row0 + arow];
    const float mx = st.x, inv = st.y;
    const unsigned dA = arow * (SROW * 2) + ak0 * 2;

    const int brow = tid >> 2;
    const int bpart = (tid & 3) * 8;
    const __half* srcBH = bHg + (long)(col0 + brow) * K + bpart;
    const __half* srcBL = bLg + (long)(col0 + brow) * K + bpart;
    const unsigned dB = brow * (SROW * 2) + bpart * 2;

    const int NIT = K / BK;
    float4 aReg[4];

#define LOADA(IT)                                                             \
    {                                                                         \
        const long ko = (long)(IT) * BK;                                      \
        _Pragma("unroll")                                                     \
        for (int i = 0; i < 4; i++)                                           \
            aReg[i] = *(const float4*)(srcA + ko + 4 * i);                    \
    }
#define STSA(STG)                                                             \
    {                                                                         \
        char* st_ = dyn + (STG) * STAGE_BYTES;                                \
        _Pragma("unroll")                                                     \
        for (int i = 0; i < 4; i++) {                                         \
            float p0 = __expf(aReg[i].x - mx) * inv;                          \
            float p1 = __expf(aReg[i].y - mx) * inv;                          \
            float p2 = __expf(aReg[i].z - mx) * inv;                          \
            float p3 = __expf(aReg[i].w - mx) * inv;                          \
            __half2 h0 = __floats2half2_rn(p0, p1);                           \
            __half2 h1 = __floats2half2_rn(p2, p3);                           \
            uint2 hh;                                                         \
            hh.x = *(unsigned*)&h0;                                           \
            hh.y = *(unsigned*)&h1;                                           \
            *(uint2*)(st_ + O_AH + dA + 8 * i) = hh;                          \
        }                                                                     \
    }
#define ISSUEB(STG, IT)                                                       \
    {                                                                         \
        const long ko = (long)(IT) * BK;                                      \
        const unsigned st = sb + (STG) * STAGE_BYTES;                         \
        cpa16(st + O_BH + dB, srcBH + ko);                                    \
        cpa16(st + O_BL + dB, srcBL + ko);                                    \
        cpa_commit();                                                         \
    }

    float acc[4][4][4] = {};

    LOADA(0); STSA(0);
    LOADA(1); STSA(1);
    ISSUEB(0, 0);
    ISSUEB(1, 1);

    int cur = 0;
    for (int it = 0; it < NIT; it++) {
        if (it + 1 < NIT) cpa_wait1(); else cpa_wait0();
        __syncthreads();

        if (it + 2 < NIT) LOADA(it + 2);

        compute_tile<PX_BL>(sb + cur * STAGE_BYTES, aoff, boff, acc);

        if (it + 2 < NIT) {
            STSA((cur + 2) % NSTAGES);
            ISSUEB((cur + 2) % NSTAGES, it + 2);
        }
        if (++cur == NSTAGES) cur = 0;
    }
#undef LOADA
#undef STSA
#undef ISSUEB

    #pragma unroll
    for (int mt = 0; mt < 4; mt++) {
        const int r = row0 + wm * 64 + mt * 16 + g;
        #pragma unroll
        for (int nt = 0; nt < 4; nt++) {
            const int c = col0 + wn * 32 + nt * 8 + 2 * t4;
            float2 v0, v1;
            v0.x = acc[mt][nt][0];
            v0.y = acc[mt][nt][1];
            v1.x = acc[mt][nt][2];
            v1.y = acc[mt][nt][3];
            *(float2*)(C + (long)r * N + c)       = v0;
            *(float2*)(C + (long)(r + 8) * N + c) = v1;
        }
    }
}

// ---------------------------------------------------------------------------
// Row stats: max + 1/sum(exp) over SEQ cols. One block per row.
// ---------------------------------------------------------------------------
__global__ __launch_bounds__(256)
void rowstat(const float* __restrict__ sim, float2* __restrict__ stats)
{
    const float* p = sim + (long)blockIdx.x * SEQ;
    const int tid = threadIdx.x;

    float v[8];
    float mx = -1e30f;
    #pragma unroll
    for (int i = 0; i < 8; i++) {
        v[i] = p[tid + i * 256];
        mx = fmaxf(mx, v[i]);
    }
    #pragma unroll
    for (int o = 16; o; o >>= 1)
        mx = fmaxf(mx, __shfl_xor_sync(0xffffffffu, mx, o));
    __shared__ float red[8];
    if ((tid & 31) == 0) red[tid >> 5] = mx;
    __syncthreads();
    mx = red[0];
    #pragma unroll
    for (int w = 1; w < 8; w++) mx = fmaxf(mx, red[w]);

    float s = 0.f;
    #pragma unroll
    for (int i = 0; i < 8; i++)
        s += __expf(v[i] - mx);
    #pragma unroll
    for (int o = 16; o; o >>= 1)
        s += __shfl_xor_sync(0xffffffffu, s, o);
    __syncthreads();
    if ((tid & 31) == 0) red[tid >> 5] = s;
    __syncthreads();
    s = red[0];
    #pragma unroll
    for (int w = 1; w < 8; w++) s += red[w];

    if (tid == 0) {
        float2 st;
        st.x = mx;
        st.y = 1.0f / s;
        stats[blockIdx.x] = st;
    }
}

// ---------------------------------------------------------------------------
// Elementwise split: fp32 -> half hi/lo
// ---------------------------------------------------------------------------
__global__ __launch_bounds__(256)
void split_hl(const float* __restrict__ in, __half* __restrict__ oH,
              __half* __restrict__ oL, long n4)
{
    const long i = (long)blockIdx.x * 256 + threadIdx.x;
    if (i >= n4) return;
    float4 v = *(const float4*)(in + 4 * i);
    uint2 hh, ll;
    split2(v.x, v.y, hh.x, ll.x);
    split2(v.z, v.w, hh.y, ll.y);
    *(uint2*)(oH + 4 * i) = hh;
    *(uint2*)(oL + 4 * i) = ll;
}

// ---------------------------------------------------------------------------
// Transpose + split: in[R,C] fp32 -> oH/oL[C,R] half (square 512x512 weights).
// ---------------------------------------------------------------------------
__global__ __launch_bounds__(256)
void transpose_split(const float* __restrict__ in,
                     __half* __restrict__ oH, __half* __restrict__ oL,
                     int R, int C)
{
    __shared__ float t[32][33];
    const int tx = threadIdx.x & 31;
    const int ty = threadIdx.x >> 5;
    const int bx = blockIdx.x * 32;
    const int by = blockIdx.y * 32;
    #pragma unroll
    for (int jj = 0; jj < 4; jj++)
        t[ty + 8 * jj][tx] = in[(long)(by + ty + 8 * jj) * C + bx + tx];
    __syncthreads();
    #pragma unroll
    for (int jj = 0; jj < 4; jj++) {
        const float f = t[tx][ty + 8 * jj];
        const __half h = __float2half_rn(f);
        const __half l = __float2half_rn(f - __half2float(h));
        const long o = (long)(bx + ty + 8 * jj) * R + by + tx;
        oH[o] = h;
        oL[o] = l;
    }
}

// ---------------------------------------------------------------------------
// V transpose from strided qkv split layout: vt[b][d][s] = v[b][s][d]
// ---------------------------------------------------------------------------
__global__ __launch_bounds__(256)
void transpose_v(const __half* __restrict__ qkvH, const __half* __restrict__ qkvL,
                 __half* __restrict__ vtH, __half* __restrict__ vtL)
{
    __shared__ float t[32][33];
    const long inB  = (long)blockIdx.z * SEQ * NQKV;
    const long outB = (long)blockIdx.z * SEQ * DIM;
    const int tx = threadIdx.x & 31;
    const int ty = threadIdx.x >> 5;
    const int bx = blockIdx.x * 32;   // d base
    const int by = blockIdx.y * 32;   // s base
    #pragma unroll
    for (int jj = 0; jj < 4; jj++) {
        const long idx = inB + (long)(by + ty + 8 * jj) * NQKV + 1024 + bx + tx;
        t[ty + 8 * jj][tx] = __half2float(qkvH[idx]) + __half2float(qkvL[idx]);
    }
    __syncthreads();
    #pragma unroll
    for (int jj = 0; jj < 4; jj++) {
        const float f = t[tx][ty + 8 * jj];
        const __half h = __float2half_rn(f);
        const __half l = __float2half_rn(f - __half2float(h));
        const long o = outB + (long)(bx + ty + 8 * jj) * SEQ + by + tx;
        vtH[o] = h;
        vtL[o] = l;
    }
}

// ---------------------------------------------------------------------------
// Bias concat: [bq | bk | bv] -> g_bias[1536]
// ---------------------------------------------------------------------------
__global__ __launch_bounds__(256)
void concat_bias(const float* __restrict__ bq, const float* __restrict__ bk,
                 const float* __restrict__ bv, float* __restrict__ b)
{
    const int i = blockIdx.x * 256 + threadIdx.x;
    if (i < 512)       b[i] = bq[i];
    else if (i < 1024) b[i] = bk[i - 512];
    else if (i < 1536) b[i] = bv[i - 1024];
}

// ---------------------------------------------------------------------------
// Launch
// ---------------------------------------------------------------------------
extern "C" void kernel_launch(void* const* d_in, const int* in_sizes, int n_in,
                              void* d_out, int out_size)
{
    const float* x  = (const float*)d_in[0];
    const float* Wq = (const float*)d_in[1];
    const float* bq = (const float*)d_in[2];
    const float* Wk = (const float*)d_in[3];
    const float* bk = (const float*)d_in[4];
    const float* Wv = (const float*)d_in[5];
    const float* bv = (const float*)d_in[6];
    float* out = (float*)d_out;

    __half *xH, *xL, *wH, *wL, *qkvH, *qkvL, *vtH, *vtL;
    float *sim, *bias;
    float2* stats;
    cudaGetSymbolAddress((void**)&xH, g_xH);
    cudaGetSymbolAddress((void**)&xL, g_xL);
    cudaGetSymbolAddress((void**)&wH, g_wH);
    cudaGetSymbolAddress((void**)&wL, g_wL);
    cudaGetSymbolAddress((void**)&bias, g_bias);
    cudaGetSymbolAddress((void**)&qkvH, g_qkvH);
    cudaGetSymbolAddress((void**)&qkvL, g_qkvL);
    cudaGetSymbolAddress((void**)&vtH, g_vtH);
    cudaGetSymbolAddress((void**)&vtL, g_vtL);
    cudaGetSymbolAddress((void**)&sim, g_sim);
    cudaGetSymbolAddress((void**)&stats, g_stats);

    cudaFuncSetAttribute(gemm_f16<1>,
                         cudaFuncAttributeMaxDynamicSharedMemorySize, SMEM_BYTES);
    cudaFuncSetAttribute(gemm_f16<0>,
                         cudaFuncAttributeMaxDynamicSharedMemorySize, SMEM_BYTES);
    cudaFuncSetAttribute(gemm_av,
                         cudaFuncAttributeMaxDynamicSharedMemorySize, SMEM_BYTES);

    // 0a) split x into half hi/lo
    {
        const long n4 = (long)MROWS * DIM / 4;
        split_hl<<<(unsigned)((n4 + 255) / 256), 256>>>(x, xH, xL, n4);
    }
    // 0b) transpose+split each weight into its [512,512] slab of [1536,512]
    {
        dim3 grid(DIM / 32, DIM / 32, 1);
        transpose_split<<<grid, 256>>>(Wq, wH, wL, DIM, DIM);
        transpose_split<<<grid, 256>>>(Wk, wH + (size_t)DIM * DIM,
                                       wL + (size_t)DIM * DIM, DIM, DIM);
        transpose_split<<<grid, 256>>>(Wv, wH + 2 * (size_t)DIM * DIM,
                                       wL + 2 * (size_t)DIM * DIM, DIM, DIM);
    }
    // 0c) bias concat
    concat_bias<<<6, 256>>>(bq, bk, bv, bias);

    // 1) Fused QKV projection: [32768,1536] = x @ [Wq|Wk|Wv]^T + bias.
    //    lo written only for V columns (>= 1024); Q/K lo is never consumed.
    {
        dim3 grid(NQKV / BN, MROWS / BM, 1);
        gemm_f16<1><<<grid, NTH, SMEM_BYTES>>>(xH, xL, wH, wL, bias,
                                               nullptr, qkvH, qkvL,
                                               MROWS, NQKV, DIM,
                                               DIM, DIM, NQKV,
                                               1.0f, 1, 1024, 0, 0, 0);
    }

    // 1b) transpose V slab -> vtH/vtL [b][d][s]
    {
        dim3 grid(DIM / 32, SEQ / 32, BATCH);
        transpose_v<<<grid, 256>>>(qkvH, qkvL, vtH, vtL);
    }

    // 2) sim[b] = Q[b] @ K[b]^T * SCALE (fp16 x1, hi parts only) -> fp32
    {
        dim3 grid(SEQ / BN, SEQ / BM, BATCH);
        gemm_f16<0><<<grid, NTH, SMEM_BYTES>>>(qkvH, nullptr,
                                               qkvH + 512, nullptr, nullptr,
                                               sim, nullptr, nullptr,
                                               SEQ, SEQ, DIM,
                                               NQKV, NQKV, SEQ,
                                               SCALE, 0, NQKV,
                                               (long)SEQ * NQKV,
                                               (long)SEQ * NQKV,
                                               (long)SEQ * SEQ);
    }

    // 3) row stats (max, 1/sum)
    rowstat<<<MROWS, 256>>>(sim, stats);

    // 4) out[b] = softmax(sim[b]) @ Vt[b]^T (x2: pH*vH + pH*vL)
    {
        dim3 grid(DIM / BN, SEQ / BM, BATCH);
        gemm_av<<<grid, NTH, SMEM_BYTES>>>(sim, stats, vtH, vtL, out,
                                           DIM, SEQ,
                                           (long)SEQ * SEQ, (long)DIM * SEQ,
                                           (long)SEQ * DIM);
    }
}

// round 16
// speedup vs baseline: 1.5599x; 1.0483x over previous
#include <cuda_runtime.h>
#include <cuda_fp16.h>
#include <cstdint>
#include <math.h>

// Problem constants
#define BATCH 16
#define SEQ   2048
#define DIM   512
#define NQKV  1536
#define MROWS (BATCH * SEQ)   // 32768
#define SCALE 0.125f

// GEMM tile config: CTA 256x128, BK=32, 512 threads (16 warps, 4x4), warp 64x32
#define BM 256
#define BN 128
#define BK 32
#define NTH 512

#define SROW 40                      // halves per row (32 + 8 pad)
#define O_AH 0
#define O_AL (BM * SROW * 2)         // 20480
#define O_BH (2 * BM * SROW * 2)     // 40960
#define O_BL (O_BH + BN * SROW * 2)  // 51200
#define STAGE_BYTES (O_BL + BN * SROW * 2)   // 61440
#define NSTAGES 3
#define SMEM_BYTES (NSTAGES * STAGE_BYTES)   // 184320

// Precision schemes for compute_tile
#define PX_HI  0   // aH*bH only
#define PX_X3  1   // aL*bH + aH*bL + aH*bH
#define PX_BL  2   // aH*bL + aH*bH  (no A-lo)

// ---------------------------------------------------------------------------
// Scratch (device globals — no allocation allowed)
// ---------------------------------------------------------------------------
__device__ __half g_xH[(size_t)MROWS * DIM];
__device__ __half g_xL[(size_t)MROWS * DIM];
__device__ __half g_wH[(size_t)NQKV * DIM];
__device__ __half g_wL[(size_t)NQKV * DIM];
__device__ float  g_bias[NQKV];
__device__ __half g_qkvH[(size_t)MROWS * NQKV];
__device__ __half g_qkvL[(size_t)MROWS * NQKV];
__device__ __half g_vtH[(size_t)MROWS * DIM];
__device__ __half g_vtL[(size_t)MROWS * DIM];
__device__ float  g_sim[(size_t)BATCH * SEQ * SEQ];
__device__ float2 g_stats[(size_t)MROWS];

// ---------------------------------------------------------------------------
// Helpers
// ---------------------------------------------------------------------------
__device__ __forceinline__ void split2(float a, float b, unsigned &h, unsigned &l) {
    __half2 hh = __floats2half2_rn(a, b);
    float2 r = __half22float2(hh);
    __half2 ll = __floats2half2_rn(a - r.x, b - r.y);
    h = *(unsigned*)&hh;
    l = *(unsigned*)&ll;
}

__device__ __forceinline__ void cpa16(unsigned dst, const void* src) {
    asm volatile("cp.async.cg.shared.global [%0], [%1], 16;"
                 :: "r"(dst), "l"(src) : "memory");
}
__device__ __forceinline__ void cpa_commit() {
    asm volatile("cp.async.commit_group;" ::: "memory");
}
__device__ __forceinline__ void cpa_wait1() {
    asm volatile("cp.async.wait_group 1;" ::: "memory");
}
__device__ __forceinline__ void cpa_wait0() {
    asm volatile("cp.async.wait_group 0;" ::: "memory");
}

#define MMA_F16(ACC, A0, A1, A2, A3, B0, B1)                                  \
    asm volatile(                                                             \
        "mma.sync.aligned.m16n8k16.row.col.f32.f16.f16.f32 "                 \
        "{%0,%1,%2,%3}, {%4,%5,%6,%7}, {%8,%9}, {%0,%1,%2,%3};"              \
        : "+f"(ACC[0]), "+f"(ACC[1]), "+f"(ACC[2]), "+f"(ACC[3])             \
        : "r"(A0), "r"(A1), "r"(A2), "r"(A3), "r"(B0), "r"(B1))

#define LDM_X4(R0, R1, R2, R3, ADDR)                                          \
    asm volatile("ldmatrix.sync.aligned.m8n8.x4.shared.b16 {%0,%1,%2,%3}, [%4];" \
        : "=r"(R0), "=r"(R1), "=r"(R2), "=r"(R3) : "r"(ADDR))

// ---------------------------------------------------------------------------
// Shared compute tile: 2 k-steps. PX selects precision scheme.
// ---------------------------------------------------------------------------
template <int PX>
__device__ __forceinline__ void compute_tile(unsigned stb, unsigned aoff,
                                             unsigned boff, float acc[4][4][4])
{
    #pragma unroll
    for (int ks = 0; ks < 2; ks++) {
        const unsigned kb = ks * 32;   // 16 halves = 32 bytes

        unsigned afH[4][4], afL[4][4];
        #pragma unroll
        for (int mt = 0; mt < 4; mt++) {
            const unsigned ah = stb + O_AH + aoff + mt * (16 * SROW * 2) + kb;
            LDM_X4(afH[mt][0], afH[mt][1], afH[mt][2], afH[mt][3], ah);
            if (PX == PX_X3) {
                const unsigned al = stb + O_AL + aoff + mt * (16 * SROW * 2) + kb;
                LDM_X4(afL[mt][0], afL[mt][1], afL[mt][2], afL[mt][3], al);
            }
        }
        unsigned bfH[4][2], bfL[4][2];
        #pragma unroll
        for (int p = 0; p < 2; p++) {
            const unsigned bh = stb + O_BH + boff + p * (16 * SROW * 2) + kb;
            LDM_X4(bfH[2*p][0], bfH[2*p][1], bfH[2*p+1][0], bfH[2*p+1][1], bh);
            if (PX == PX_X3 || PX == PX_BL) {
                const unsigned bl = stb + O_BL + boff + p * (16 * SROW * 2) + kb;
                LDM_X4(bfL[2*p][0], bfL[2*p][1], bfL[2*p+1][0], bfL[2*p+1][1], bl);
            }
        }
        #pragma unroll
        for (int mt = 0; mt < 4; mt++)
            #pragma unroll
            for (int nt = 0; nt < 4; nt++) {
                float* a4 = acc[mt][nt];
                if (PX == PX_X3) {
                    MMA_F16(a4, afL[mt][0], afL[mt][1], afL[mt][2], afL[mt][3],
                            bfH[nt][0], bfH[nt][1]);
                }
                if (PX == PX_X3 || PX == PX_BL) {
                    MMA_F16(a4, afH[mt][0], afH[mt][1], afH[mt][2], afH[mt][3],
                            bfL[nt][0], bfL[nt][1]);
                }
                MMA_F16(a4, afH[mt][0], afH[mt][1], afH[mt][2], afH[mt][3],
                        bfH[nt][0], bfH[nt][1]);
            }
    }
}

// Per-thread ldmatrix offsets.
__device__ __forceinline__ void frag_offsets(int warp, int lane,
                                             unsigned &aoff, unsigned &boff)
{
    const int wm = warp >> 2, wn = warp & 3;
    const int t8 = lane >> 3, r8 = lane & 7;
    aoff = ((wm * 64 + ((t8 & 1) << 3) + r8) * SROW + ((t8 >> 1) << 3)) * 2;
    boff = ((wn * 32 + ((t8 >> 1) << 3) + r8) * SROW + ((t8 & 1) << 3)) * 2;
}

// ---------------------------------------------------------------------------
// NT GEMM with cp.async pipeline. X3: 1 -> split inputs, 0 -> hi-only.
// C[M,N] = alpha * A[M,K(ldA)] * (B[N,K(ldB)])^T + bias
// mode 0: write fp32 C (ldC).  mode 1: write split half oH/oL (ldC);
//         lo written only for columns >= loMinCol.
// x3MinCol (X3 only): tiles with col0 < x3MinCol use PX_BL (drop aL term);
//         tiles with col0 >= x3MinCol use full PX_X3.
// ---------------------------------------------------------------------------
template <int X3>
__global__ __launch_bounds__(NTH, 1)
void gemm_f16(const __half* __restrict__ aHg, const __half* __restrict__ aLg,
              const __half* __restrict__ bHg, const __half* __restrict__ bLg,
              const float* __restrict__ bias, float* __restrict__ C,
              __half* __restrict__ oH, __half* __restrict__ oL,
              int M, int N, int K, int ldA, int ldB, int ldC,
              float alpha, int mode, int loMinCol, int x3MinCol,
              long sA, long sB, long sC)
{
    extern __shared__ __align__(16) char dyn[];

    const long zb = blockIdx.z;
    aHg += zb * sA; if (X3) aLg += zb * sA;
    bHg += zb * sB; if (X3) bLg += zb * sB;
    if (C)  C  += zb * sC;
    if (oH) { oH += zb * sC; oL += zb * sC; }

    const int tid  = threadIdx.x;
    const int row0 = blockIdx.y * BM;
    const int col0 = blockIdx.x * BN;

    const int warp = tid >> 5;
    const int lane = tid & 31;
    const int wm   = warp >> 2;
    const int wn   = warp & 3;
    const int g    = lane >> 2;
    const int t4   = lane & 3;

    const bool useAL = X3 && (col0 >= x3MinCol);

    const unsigned sb = (unsigned)__cvta_generic_to_shared(dyn);
    unsigned aoff, boff;
    frag_offsets(warp, lane, aoff, boff);

    const int arow0 = tid >> 2;
    const int apart = (tid & 3) * 8;
    const __half* srcAH0 = aHg + (long)(row0 + arow0) * ldA + apart;
    const __half* srcAH1 = aHg + (long)(row0 + 128 + arow0) * ldA + apart;
    const __half* srcAL0 = X3 ? (aLg + (long)(row0 + arow0) * ldA + apart) : srcAH0;
    const __half* srcAL1 = X3 ? (aLg + (long)(row0 + 128 + arow0) * ldA + apart) : srcAH1;
    const __half* srcBH  = bHg + (long)(col0 + arow0) * ldB + apart;
    const __half* srcBL  = X3 ? (bLg + (long)(col0 + arow0) * ldB + apart) : srcBH;
    const unsigned dA0 = arow0 * (SROW * 2) + apart * 2;
    const unsigned dA1 = (128 + arow0) * (SROW * 2) + apart * 2;
    const unsigned dB  = arow0 * (SROW * 2) + apart * 2;

    const int NIT = K / BK;

#define ISSUE(STG, IT)                                                        \
    {                                                                         \
        const long ko = (long)(IT) * BK;                                      \
        const unsigned st = sb + (STG) * STAGE_BYTES;                         \
        cpa16(st + O_AH + dA0, srcAH0 + ko);                                  \
        cpa16(st + O_AH + dA1, srcAH1 + ko);                                  \
        cpa16(st + O_BH + dB,  srcBH  + ko);                                  \
        if (X3) {                                                             \
            cpa16(st + O_BL + dB,  srcBL  + ko);                              \
            if (useAL) {                                                      \
                cpa16(st + O_AL + dA0, srcAL0 + ko);                          \
                cpa16(st + O_AL + dA1, srcAL1 + ko);                          \
            }                                                                 \
        }                                                                     \
        cpa_commit();                                                         \
    }

    float acc[4][4][4] = {};

    ISSUE(0, 0);
    ISSUE(1, 1);

    int cur = 0;
    for (int it = 0; it < NIT; it++) {
        if (it + 1 < NIT) cpa_wait1(); else cpa_wait0();
        __syncthreads();

        if (X3) {
            if (useAL)
                compute_tile<PX_X3>(sb + cur * STAGE_BYTES, aoff, boff, acc);
            else
                compute_tile<PX_BL>(sb + cur * STAGE_BYTES, aoff, boff, acc);
        } else {
            compute_tile<PX_HI>(sb + cur * STAGE_BYTES, aoff, boff, acc);
        }

        if (it + 2 < NIT) ISSUE((cur + 2) % NSTAGES, it + 2);
        if (++cur == NSTAGES) cur = 0;
    }
#undef ISSUE

    // ---- epilogue ----
    const bool wantLo = (col0 + BN > loMinCol);
    #pragma unroll
    for (int mt = 0; mt < 4; mt++) {
        const int r = row0 + wm * 64 + mt * 16 + g;
        #pragma unroll
        for (int nt = 0; nt < 4; nt++) {
            const int c = col0 + wn * 32 + nt * 8 + 2 * t4;
            float b0 = 0.f, b1 = 0.f;
            if (bias) { b0 = bias[c]; b1 = bias[c + 1]; }
            float2 v0, v1;
            v0.x = alpha * acc[mt][nt][0] + b0;
            v0.y = alpha * acc[mt][nt][1] + b1;
            v1.x = alpha * acc[mt][nt][2] + b0;
            v1.y = alpha * acc[mt][nt][3] + b1;
            if (mode == 0) {
                *(float2*)(C + (long)r * ldC + c)       = v0;
                *(float2*)(C + (long)(r + 8) * ldC + c) = v1;
            } else {
                unsigned h, l;
                split2(v0.x, v0.y, h, l);
                *(unsigned*)(oH + (long)r * ldC + c) = h;
                if (wantLo) *(unsigned*)(oL + (long)r * ldC + c) = l;
                split2(v1.x, v1.y, h, l);
                *(unsigned*)(oH + (long)(r + 8) * ldC + c) = h;
                if (wantLo) *(unsigned*)(oL + (long)(r + 8) * ldC + c) = l;
            }
        }
    }
}

// ---------------------------------------------------------------------------
// Fused attn@V GEMM: A = softmax(sim) on the fly (hi only); B = Vt split.
// Precision PX_BL: pH*vL + pH*vH.
// ---------------------------------------------------------------------------
__global__ __launch_bounds__(NTH, 1)
void gemm_av(const float* __restrict__ sim, const float2* __restrict__ stats,
             const __half* __restrict__ bHg, const __half* __restrict__ bLg,
             float* __restrict__ C, int N, int K,
             long sA, long sB, long sC)
{
    extern __shared__ __align__(16) char dyn[];

    const long zb = blockIdx.z;
    sim += zb * sA;
    bHg += zb * sB; bLg += zb * sB;
    C   += zb * sC;

    const int tid  = threadIdx.x;
    const int row0 = blockIdx.y * BM;
    const int col0 = blockIdx.x * BN;

    const int warp = tid >> 5;
    const int lane = tid & 31;
    const int wm   = warp >> 2;
    const int wn   = warp & 3;
    const int g    = lane >> 2;
    const int t4   = lane & 3;

    const unsigned sb = (unsigned)__cvta_generic_to_shared(dyn);
    unsigned aoff, boff;
    frag_offsets(warp, lane, aoff, boff);

    const int arow = tid >> 1;
    const int ak0  = (tid & 1) * 16;
    const float* srcA = sim + (long)(row0 + arow) * K + ak0;
    const float2 st = stats[zb * SEQ + row0 + arow];
    const float mx = st.x, inv = st.y;
    const unsigned dA = arow * (SROW * 2) + ak0 * 2;

    const int brow = tid >> 2;
    const int bpart = (tid & 3) * 8;
    const __half* srcBH = bHg + (long)(col0 + brow) * K + bpart;
    const __half* srcBL = bLg + (long)(col0 + brow) * K + bpart;
    const unsigned dB = brow * (SROW * 2) + bpart * 2;

    const int NIT = K / BK;
    float4 aReg[4];

#define LOADA(IT)                                                             \
    {                                                                         \
        const long ko = (long)(IT) * BK;                                      \
        _Pragma("unroll")                                                     \
        for (int i = 0; i < 4; i++)                                           \
            aReg[i] = *(const float4*)(srcA + ko + 4 * i);                    \
    }
#define STSA(STG)                                                             \
    {                                                                         \
        char* st_ = dyn + (STG) * STAGE_BYTES;                                \
        _Pragma("unroll")                                                     \
        for (int i = 0; i < 4; i++) {                                         \
            float p0 = __expf(aReg[i].x - mx) * inv;                          \
            float p1 = __expf(aReg[i].y - mx) * inv;                          \
            float p2 = __expf(aReg[i].z - mx) * inv;                          \
            float p3 = __expf(aReg[i].w - mx) * inv;                          \
            __half2 h0 = __floats2half2_rn(p0, p1);                           \
            __half2 h1 = __floats2half2_rn(p2, p3);                           \
            uint2 hh;                                                         \
            hh.x = *(unsigned*)&h0;                                           \
            hh.y = *(unsigned*)&h1;                                           \
            *(uint2*)(st_ + O_AH + dA + 8 * i) = hh;                          \
        }                                                                     \
    }
#define ISSUEB(STG, IT)                                                       \
    {                                                                         \
        const long ko = (long)(IT) * BK;                                      \
        const unsigned st = sb + (STG) * STAGE_BYTES;                         \
        cpa16(st + O_BH + dB, srcBH + ko);                                    \
        cpa16(st + O_BL + dB, srcBL + ko);                                    \
        cpa_commit();                                                         \
    }

    float acc[4][4][4] = {};

    LOADA(0); STSA(0);
    LOADA(1); STSA(1);
    ISSUEB(0, 0);
    ISSUEB(1, 1);

    int cur = 0;
    for (int it = 0; it < NIT; it++) {
        if (it + 1 < NIT) cpa_wait1(); else cpa_wait0();
        __syncthreads();

        if (it + 2 < NIT) LOADA(it + 2);

        compute_tile<PX_BL>(sb + cur * STAGE_BYTES, aoff, boff, acc);

        if (it + 2 < NIT) {
            STSA((cur + 2) % NSTAGES);
            ISSUEB((cur + 2) % NSTAGES, it + 2);
        }
        if (++cur == NSTAGES) cur = 0;
    }
#undef LOADA
#undef STSA
#undef ISSUEB

    #pragma unroll
    for (int mt = 0; mt < 4; mt++) {
        const int r = row0 + wm * 64 + mt * 16 + g;
        #pragma unroll
        for (int nt = 0; nt < 4; nt++) {
            const int c = col0 + wn * 32 + nt * 8 + 2 * t4;
            float2 v0, v1;
            v0.x = acc[mt][nt][0];
            v0.y = acc[mt][nt][1];
            v1.x = acc[mt][nt][2];
            v1.y = acc[mt][nt][3];
            *(float2*)(C + (long)r * N + c)       = v0;
            *(float2*)(C + (long)(r + 8) * N + c) = v1;
        }
    }
}

// ---------------------------------------------------------------------------
// Row stats: max + 1/sum(exp) over SEQ cols. One block per row.
// ---------------------------------------------------------------------------
__global__ __launch_bounds__(256)
void rowstat(const float* __restrict__ sim, float2* __restrict__ stats)
{
    const float* p = sim + (long)blockIdx.x * SEQ;
    const int tid = threadIdx.x;

    float v[8];
    float mx = -1e30f;
    #pragma unroll
    for (int i = 0; i < 8; i++) {
        v[i] = p[tid + i * 256];
        mx = fmaxf(mx, v[i]);
    }
    #pragma unroll
    for (int o = 16; o; o >>= 1)
        mx = fmaxf(mx, __shfl_xor_sync(0xffffffffu, mx, o));
    __shared__ float red[8];
    if ((tid & 31) == 0) red[tid >> 5] = mx;
    __syncthreads();
    mx = red[0];
    #pragma unroll
    for (int w = 1; w < 8; w++) mx = fmaxf(mx, red[w]);

    float s = 0.f;
    #pragma unroll
    for (int i = 0; i < 8; i++)
        s += __expf(v[i] - mx);
    #pragma unroll
    for (int o = 16; o; o >>= 1)
        s += __shfl_xor_sync(0xffffffffu, s, o);
    __syncthreads();
    if ((tid & 31) == 0) red[tid >> 5] = s;
    __syncthreads();
    s = red[0];
    #pragma unroll
    for (int w = 1; w < 8; w++) s += red[w];

    if (tid == 0) {
        float2 st;
        st.x = mx;
        st.y = 1.0f / s;
        stats[blockIdx.x] = st;
    }
}

// ---------------------------------------------------------------------------
// Elementwise split: fp32 -> half hi/lo
// ---------------------------------------------------------------------------
__global__ __launch_bounds__(256)
void split_hl(const float* __restrict__ in, __half* __restrict__ oH,
              __half* __restrict__ oL, long n4)
{
    const long i = (long)blockIdx.x * 256 + threadIdx.x;
    if (i >= n4) return;
    float4 v = *(const float4*)(in + 4 * i);
    uint2 hh, ll;
    split2(v.x, v.y, hh.x, ll.x);
    split2(v.z, v.w, hh.y, ll.y);
    *(uint2*)(oH + 4 * i) = hh;
    *(uint2*)(oL + 4 * i) = ll;
}

// ---------------------------------------------------------------------------
// Transpose + split: in[R,C] fp32 -> oH/oL[C,R] half (square 512x512 weights).
// ---------------------------------------------------------------------------
__global__ __launch_bounds__(256)
void transpose_split(const float* __restrict__ in,
                     __half* __restrict__ oH, __half* __restrict__ oL,
                     int R, int C)
{
    __shared__ float t[32][33];
    const int tx = threadIdx.x & 31;
    const int ty = threadIdx.x >> 5;
    const int bx = blockIdx.x * 32;
    const int by = blockIdx.y * 32;
    #pragma unroll
    for (int jj = 0; jj < 4; jj++)
        t[ty + 8 * jj][tx] = in[(long)(by + ty + 8 * jj) * C + bx + tx];
    __syncthreads();
    #pragma unroll
    for (int jj = 0; jj < 4; jj++) {
        const float f = t[tx][ty + 8 * jj];
        const __half h = __float2half_rn(f);
        const __half l = __float2half_rn(f - __half2float(h));
        const long o = (long)(bx + ty + 8 * jj) * R + by + tx;
        oH[o] = h;
        oL[o] = l;
    }
}

// ---------------------------------------------------------------------------
// V transpose from strided qkv split layout: vt[b][d][s] = v[b][s][d]
// ---------------------------------------------------------------------------
__global__ __launch_bounds__(256)
void transpose_v(const __half* __restrict__ qkvH, const __half* __restrict__ qkvL,
                 __half* __restrict__ vtH, __half* __restrict__ vtL)
{
    __shared__ float t[32][33];
    const long inB  = (long)blockIdx.z * SEQ * NQKV;
    const long outB = (long)blockIdx.z * SEQ * DIM;
    const int tx = threadIdx.x & 31;
    const int ty = threadIdx.x >> 5;
    const int bx = blockIdx.x * 32;   // d base
    const int by = blockIdx.y * 32;   // s base
    #pragma unroll
    for (int jj = 0; jj < 4; jj++) {
        const long idx = inB + (long)(by + ty + 8 * jj) * NQKV + 1024 + bx + tx;
        t[ty + 8 * jj][tx] = __half2float(qkvH[idx]) + __half2float(qkvL[idx]);
    }
    __syncthreads();
    #pragma unroll
    for (int jj = 0; jj < 4; jj++) {
        const float f = t[tx][ty + 8 * jj];
        const __half h = __float2half_rn(f);
        const __half l = __float2half_rn(f - __half2float(h));
        const long o = outB + (long)(bx + ty + 8 * jj) * SEQ + by + tx;
        vtH[o] = h;
        vtL[o] = l;
    }
}

// ---------------------------------------------------------------------------
// Bias concat: [bq | bk | bv] -> g_bias[1536]
// ---------------------------------------------------------------------------
__global__ __launch_bounds__(256)
void concat_bias(const float* __restrict__ bq, const float* __restrict__ bk,
                 const float* __restrict__ bv, float* __restrict__ b)
{
    const int i = blockIdx.x * 256 + threadIdx.x;
    if (i < 512)       b[i] = bq[i];
    else if (i < 1024) b[i] = bk[i - 512];
    else if (i < 1536) b[i] = bv[i - 1024];
}

// ---------------------------------------------------------------------------
// Launch
// ---------------------------------------------------------------------------
extern "C" void kernel_launch(void* const* d_in, const int* in_sizes, int n_in,
                              void* d_out, int out_size)
{
    const float* x  = (const float*)d_in[0];
    const float* Wq = (const float*)d_in[1];
    const float* bq = (const float*)d_in[2];
    const float* Wk = (const float*)d_in[3];
    const float* bk = (const float*)d_in[4];
    const float* Wv = (const float*)d_in[5];
    const float* bv = (const float*)d_in[6];
    float* out = (float*)d_out;

    __half *xH, *xL, *wH, *wL, *qkvH, *qkvL, *vtH, *vtL;
    float *sim, *bias;
    float2* stats;
    cudaGetSymbolAddress((void**)&xH, g_xH);
    cudaGetSymbolAddress((void**)&xL, g_xL);
    cudaGetSymbolAddress((void**)&wH, g_wH);
    cudaGetSymbolAddress((void**)&wL, g_wL);
    cudaGetSymbolAddress((void**)&bias, g_bias);
    cudaGetSymbolAddress((void**)&qkvH, g_qkvH);
    cudaGetSymbolAddress((void**)&qkvL, g_qkvL);
    cudaGetSymbolAddress((void**)&vtH, g_vtH);
    cudaGetSymbolAddress((void**)&vtL, g_vtL);
    cudaGetSymbolAddress((void**)&sim, g_sim);
    cudaGetSymbolAddress((void**)&stats, g_stats);

    cudaFuncSetAttribute(gemm_f16<1>,
                         cudaFuncAttributeMaxDynamicSharedMemorySize, SMEM_BYTES);
    cudaFuncSetAttribute(gemm_f16<0>,
                         cudaFuncAttributeMaxDynamicSharedMemorySize, SMEM_BYTES);
    cudaFuncSetAttribute(gemm_av,
                         cudaFuncAttributeMaxDynamicSharedMemorySize, SMEM_BYTES);

    // 0a) split x into half hi/lo
    {
        const long n4 = (long)MROWS * DIM / 4;
        split_hl<<<(unsigned)((n4 + 255) / 256), 256>>>(x, xH, xL, n4);
    }
    // 0b) transpose+split each weight into its [512,512] slab of [1536,512]
    {
        dim3 grid(DIM / 32, DIM / 32, 1);
        transpose_split<<<grid, 256>>>(Wq, wH, wL, DIM, DIM);
        transpose_split<<<grid, 256>>>(Wk, wH + (size_t)DIM * DIM,
                                       wL + (size_t)DIM * DIM, DIM, DIM);
        transpose_split<<<grid, 256>>>(Wv, wH + 2 * (size_t)DIM * DIM,
                                       wL + 2 * (size_t)DIM * DIM, DIM, DIM);
    }
    // 0c) bias concat
    concat_bias<<<6, 256>>>(bq, bk, bv, bias);

    // 1) Fused QKV projection: [32768,1536] = x @ [Wq|Wk|Wv]^T + bias.
    //    Q/K slabs (cols < 1024): x2 precision (drop xL term), no lo stores.
    //    V slab (cols >= 1024): full x3, split hi/lo output.
    {
        dim3 grid(NQKV / BN, MROWS / BM, 1);
        gemm_f16<1><<<grid, NTH, SMEM_BYTES>>>(xH, xL, wH, wL, bias,
                                               nullptr, qkvH, qkvL,
                                               MROWS, NQKV, DIM,
                                               DIM, DIM, NQKV,
                                               1.0f, 1, 1024, 1024, 0, 0, 0);
    }

    // 1b) transpose V slab -> vtH/vtL [b][d][s]
    {
        dim3 grid(DIM / 32, SEQ / 32, BATCH);
        transpose_v<<<grid, 256>>>(qkvH, qkvL, vtH, vtL);
    }

    // 2) sim[b] = Q[b] @ K[b]^T * SCALE (fp16 x1, hi parts only) -> fp32
    {
        dim3 grid(SEQ / BN, SEQ / BM, BATCH);
        gemm_f16<0><<<grid, NTH, SMEM_BYTES>>>(qkvH, nullptr,
                                               qkvH + 512, nullptr, nullptr,
                                               sim, nullptr, nullptr,
                                               SEQ, SEQ, DIM,
                                               NQKV, NQKV, SEQ,
                                               SCALE, 0, NQKV, 0,
                                               (long)SEQ * NQKV,
                                               (long)SEQ * NQKV,
                                               (long)SEQ * SEQ);
    }

    // 3) row stats (max, 1/sum)
    rowstat<<<MROWS, 256>>>(sim, stats);

    // 4) out[b] = softmax(sim[b]) @ Vt[b]^T (x2: pH*vH + pH*vL)
    {
        dim3 grid(DIM / BN, SEQ / BM, BATCH);
        gemm_av<<<grid, NTH, SMEM_BYTES>>>(sim, stats, vtH, vtL, out,
                                           DIM, SEQ,
                                           (long)SEQ * SEQ, (long)DIM * SEQ,
                                           (long)SEQ * DIM);
    }
}

// round 17
// speedup vs baseline: 1.6539x; 1.0603x over previous
#include <cuda_runtime.h>
#include <cuda_fp16.h>
#include <cstdint>
#include <math.h>

// Problem constants
#define BATCH 16
#define SEQ   2048
#define DIM   512
#define NQKV  1536
#define MROWS (BATCH * SEQ)   // 32768
#define SCALE 0.125f

// GEMM tile config: CTA 256x128, BK=32, 512 threads (16 warps, 4x4), warp 64x32
#define BM 256
#define BN 128
#define BK 32
#define NTH 512

#define SROW 40                      // halves per row (32 + 8 pad)
#define O_AH 0
#define O_AL (BM * SROW * 2)         // 20480
#define O_BH (2 * BM * SROW * 2)     // 40960
#define O_BL (O_BH + BN * SROW * 2)  // 51200
#define STAGE_BYTES (O_BL + BN * SROW * 2)   // 61440
#define NSTAGES 3
#define SMEM_BYTES (NSTAGES * STAGE_BYTES)   // 184320

// Precision schemes for compute_tile
#define PX_HI  0   // aH*bH only
#define PX_X3  1   // aL*bH + aH*bL + aH*bH
#define PX_BL  2   // aH*bL + aH*bH  (no A-lo)

// gemm_f16 template flavors
//  X3=0: A hi, B hi            (sim)
//  X3=1: A split, B split      (QKV; x3MinCol selects PX_X3 vs PX_BL per tile)
//  X3=2: A hi, B split, PX_BL  (AV)

// ---------------------------------------------------------------------------
// Scratch (device globals — no allocation allowed)
// ---------------------------------------------------------------------------
__device__ __half g_xH[(size_t)MROWS * DIM];
__device__ __half g_xL[(size_t)MROWS * DIM];
__device__ __half g_wH[(size_t)NQKV * DIM];
__device__ __half g_wL[(size_t)NQKV * DIM];
__device__ float  g_bias[NQKV];
__device__ __half g_qkvH[(size_t)MROWS * NQKV];
__device__ __half g_qkvL[(size_t)MROWS * NQKV];
__device__ __half g_vtH[(size_t)MROWS * DIM];
__device__ __half g_vtL[(size_t)MROWS * DIM];
__device__ float  g_sim[(size_t)BATCH * SEQ * SEQ];
__device__ __half g_p[(size_t)BATCH * SEQ * SEQ];

// ---------------------------------------------------------------------------
// Helpers
// ---------------------------------------------------------------------------
__device__ __forceinline__ void split2(float a, float b, unsigned &h, unsigned &l) {
    __half2 hh = __floats2half2_rn(a, b);
    float2 r = __half22float2(hh);
    __half2 ll = __floats2half2_rn(a - r.x, b - r.y);
    h = *(unsigned*)&hh;
    l = *(unsigned*)&ll;
}

__device__ __forceinline__ void cpa16(unsigned dst, const void* src) {
    asm volatile("cp.async.cg.shared.global [%0], [%1], 16;"
                 :: "r"(dst), "l"(src) : "memory");
}
__device__ __forceinline__ void cpa_commit() {
    asm volatile("cp.async.commit_group;" ::: "memory");
}
__device__ __forceinline__ void cpa_wait1() {
    asm volatile("cp.async.wait_group 1;" ::: "memory");
}
__device__ __forceinline__ void cpa_wait0() {
    asm volatile("cp.async.wait_group 0;" ::: "memory");
}

#define MMA_F16(ACC, A0, A1, A2, A3, B0, B1)                                  \
    asm volatile(                                                             \
        "mma.sync.aligned.m16n8k16.row.col.f32.f16.f16.f32 "                 \
        "{%0,%1,%2,%3}, {%4,%5,%6,%7}, {%8,%9}, {%0,%1,%2,%3};"              \
        : "+f"(ACC[0]), "+f"(ACC[1]), "+f"(ACC[2]), "+f"(ACC[3])             \
        : "r"(A0), "r"(A1), "r"(A2), "r"(A3), "r"(B0), "r"(B1))

#define LDM_X4(R0, R1, R2, R3, ADDR)                                          \
    asm volatile("ldmatrix.sync.aligned.m8n8.x4.shared.b16 {%0,%1,%2,%3}, [%4];" \
        : "=r"(R0), "=r"(R1), "=r"(R2), "=r"(R3) : "r"(ADDR))

// ---------------------------------------------------------------------------
// Shared compute tile: 2 k-steps. PX selects precision scheme.
// ---------------------------------------------------------------------------
template <int PX>
__device__ __forceinline__ void compute_tile(unsigned stb, unsigned aoff,
                                             unsigned boff, float acc[4][4][4])
{
    #pragma unroll
    for (int ks = 0; ks < 2; ks++) {
        const unsigned kb = ks * 32;   // 16 halves = 32 bytes

        unsigned afH[4][4], afL[4][4];
        #pragma unroll
        for (int mt = 0; mt < 4; mt++) {
            const unsigned ah = stb + O_AH + aoff + mt * (16 * SROW * 2) + kb;
            LDM_X4(afH[mt][0], afH[mt][1], afH[mt][2], afH[mt][3], ah);
            if (PX == PX_X3) {
                const unsigned al = stb + O_AL + aoff + mt * (16 * SROW * 2) + kb;
                LDM_X4(afL[mt][0], afL[mt][1], afL[mt][2], afL[mt][3], al);
            }
        }
        unsigned bfH[4][2], bfL[4][2];
        #pragma unroll
        for (int p = 0; p < 2; p++) {
            const unsigned bh = stb + O_BH + boff + p * (16 * SROW * 2) + kb;
            LDM_X4(bfH[2*p][0], bfH[2*p][1], bfH[2*p+1][0], bfH[2*p+1][1], bh);
            if (PX == PX_X3 || PX == PX_BL) {
                const unsigned bl = stb + O_BL + boff + p * (16 * SROW * 2) + kb;
                LDM_X4(bfL[2*p][0], bfL[2*p][1], bfL[2*p+1][0], bfL[2*p+1][1], bl);
            }
        }
        #pragma unroll
        for (int mt = 0; mt < 4; mt++)
            #pragma unroll
            for (int nt = 0; nt < 4; nt++) {
                float* a4 = acc[mt][nt];
                if (PX == PX_X3) {
                    MMA_F16(a4, afL[mt][0], afL[mt][1], afL[mt][2], afL[mt][3],
                            bfH[nt][0], bfH[nt][1]);
                }
                if (PX == PX_X3 || PX == PX_BL) {
                    MMA_F16(a4, afH[mt][0], afH[mt][1], afH[mt][2], afH[mt][3],
                            bfL[nt][0], bfL[nt][1]);
                }
                MMA_F16(a4, afH[mt][0], afH[mt][1], afH[mt][2], afH[mt][3],
                        bfH[nt][0], bfH[nt][1]);
            }
    }
}

// Per-thread ldmatrix offsets.
__device__ __forceinline__ void frag_offsets(int warp, int lane,
                                             unsigned &aoff, unsigned &boff)
{
    const int wm = warp >> 2, wn = warp & 3;
    const int t8 = lane >> 3, r8 = lane & 7;
    aoff = ((wm * 64 + ((t8 & 1) << 3) + r8) * SROW + ((t8 >> 1) << 3)) * 2;
    boff = ((wn * 32 + ((t8 >> 1) << 3) + r8) * SROW + ((t8 & 1) << 3)) * 2;
}

// ---------------------------------------------------------------------------
// NT GEMM with cp.async pipeline.
// C[M,N] = alpha * A[M,K(ldA)] * (B[N,K(ldB)])^T + bias
// mode 0: write fp32 C (ldC).  mode 1: write split half oH/oL (ldC);
//         lo written only for columns >= loMinCol.
// x3MinCol (X3==1 only): tiles with col0 < x3MinCol use PX_BL.
// ---------------------------------------------------------------------------
template <int X3>
__global__ __launch_bounds__(NTH, 1)
void gemm_f16(const __half* __restrict__ aHg, const __half* __restrict__ aLg,
              const __half* __restrict__ bHg, const __half* __restrict__ bLg,
              const float* __restrict__ bias, float* __restrict__ C,
              __half* __restrict__ oH, __half* __restrict__ oL,
              int M, int N, int K, int ldA, int ldB, int ldC,
              float alpha, int mode, int loMinCol, int x3MinCol,
              long sA, long sB, long sC)
{
    extern __shared__ __align__(16) char dyn[];

    const long zb = blockIdx.z;
    aHg += zb * sA; if (X3 == 1) aLg += zb * sA;
    bHg += zb * sB; if (X3 >= 1) bLg += zb * sB;
    if (C)  C  += zb * sC;
    if (oH) { oH += zb * sC; oL += zb * sC; }

    const int tid  = threadIdx.x;
    const int row0 = blockIdx.y * BM;
    const int col0 = blockIdx.x * BN;

    const int warp = tid >> 5;
    const int lane = tid & 31;
    const int wm   = warp >> 2;
    const int wn   = warp & 3;
    const int g    = lane >> 2;
    const int t4   = lane & 3;

    const bool useAL = (X3 == 1) && (col0 >= x3MinCol);

    const unsigned sb = (unsigned)__cvta_generic_to_shared(dyn);
    unsigned aoff, boff;
    frag_offsets(warp, lane, aoff, boff);

    const int arow0 = tid >> 2;
    const int apart = (tid & 3) * 8;
    const __half* srcAH0 = aHg + (long)(row0 + arow0) * ldA + apart;
    const __half* srcAH1 = aHg + (long)(row0 + 128 + arow0) * ldA + apart;
    const __half* srcAL0 = (X3 == 1) ? (aLg + (long)(row0 + arow0) * ldA + apart) : srcAH0;
    const __half* srcAL1 = (X3 == 1) ? (aLg + (long)(row0 + 128 + arow0) * ldA + apart) : srcAH1;
    const __half* srcBH  = bHg + (long)(col0 + arow0) * ldB + apart;
    const __half* srcBL  = (X3 >= 1) ? (bLg + (long)(col0 + arow0) * ldB + apart) : srcBH;
    const unsigned dA0 = arow0 * (SROW * 2) + apart * 2;
    const unsigned dA1 = (128 + arow0) * (SROW * 2) + apart * 2;
    const unsigned dB  = arow0 * (SROW * 2) + apart * 2;

    const int NIT = K / BK;

#define ISSUE(STG, IT)                                                        \
    {                                                                         \
        const long ko = (long)(IT) * BK;                                      \
        const unsigned st = sb + (STG) * STAGE_BYTES;                         \
        cpa16(st + O_AH + dA0, srcAH0 + ko);                                  \
        cpa16(st + O_AH + dA1, srcAH1 + ko);                                  \
        cpa16(st + O_BH + dB,  srcBH  + ko);                                  \
        if (X3 >= 1) {                                                        \
            cpa16(st + O_BL + dB,  srcBL  + ko);                              \
            if (useAL) {                                                      \
                cpa16(st + O_AL + dA0, srcAL0 + ko);                          \
                cpa16(st + O_AL + dA1, srcAL1 + ko);                          \
            }                                                                 \
        }                                                                     \
        cpa_commit();                                                         \
    }

    float acc[4][4][4] = {};

    ISSUE(0, 0);
    ISSUE(1, 1);

    int cur = 0;
    for (int it = 0; it < NIT; it++) {
        if (it + 1 < NIT) cpa_wait1(); else cpa_wait0();
        __syncthreads();

        if (X3 == 0) {
            compute_tile<PX_HI>(sb + cur * STAGE_BYTES, aoff, boff, acc);
        } else if (X3 == 2) {
            compute_tile<PX_BL>(sb + cur * STAGE_BYTES, aoff, boff, acc);
        } else {
            if (useAL)
                compute_tile<PX_X3>(sb + cur * STAGE_BYTES, aoff, boff, acc);
            else
                compute_tile<PX_BL>(sb + cur * STAGE_BYTES, aoff, boff, acc);
        }

        if (it + 2 < NIT) ISSUE((cur + 2) % NSTAGES, it + 2);
        if (++cur == NSTAGES) cur = 0;
    }
#undef ISSUE

    // ---- epilogue ----
    const bool wantLo = (col0 + BN > loMinCol);
    #pragma unroll
    for (int mt = 0; mt < 4; mt++) {
        const int r = row0 + wm * 64 + mt * 16 + g;
        #pragma unroll
        for (int nt = 0; nt < 4; nt++) {
            const int c = col0 + wn * 32 + nt * 8 + 2 * t4;
            float b0 = 0.f, b1 = 0.f;
            if (bias) { b0 = bias[c]; b1 = bias[c + 1]; }
            float2 v0, v1;
            v0.x = alpha * acc[mt][nt][0] + b0;
            v0.y = alpha * acc[mt][nt][1] + b1;
            v1.x = alpha * acc[mt][nt][2] + b0;
            v1.y = alpha * acc[mt][nt][3] + b1;
            if (mode == 0) {
                *(float2*)(C + (long)r * ldC + c)       = v0;
                *(float2*)(C + (long)(r + 8) * ldC + c) = v1;
            } else {
                unsigned h, l;
                split2(v0.x, v0.y, h, l);
                *(unsigned*)(oH + (long)r * ldC + c) = h;
                if (wantLo) *(unsigned*)(oL + (long)r * ldC + c) = l;
                split2(v1.x, v1.y, h, l);
                *(unsigned*)(oH + (long)(r + 8) * ldC + c) = h;
                if (wantLo) *(unsigned*)(oL + (long)(r + 8) * ldC + c) = l;
            }
        }
    }
}

// ---------------------------------------------------------------------------
// Softmax pass: per row, compute max + 1/sum(exp) and write P as fp16.
// One block (256 threads) per row.
// ---------------------------------------------------------------------------
__global__ __launch_bounds__(256)
void softmax_p(const float* __restrict__ sim, __half* __restrict__ pOut)
{
    const float* p = sim + (long)blockIdx.x * SEQ;
    __half* po = pOut + (long)blockIdx.x * SEQ;
    const int tid = threadIdx.x;

    float v[8];
    float mx = -1e30f;
    #pragma unroll
    for (int i = 0; i < 8; i++) {
        v[i] = p[tid + i * 256];
        mx = fmaxf(mx, v[i]);
    }
    #pragma unroll
    for (int o = 16; o; o >>= 1)
        mx = fmaxf(mx, __shfl_xor_sync(0xffffffffu, mx, o));
    __shared__ float red[8];
    if ((tid & 31) == 0) red[tid >> 5] = mx;
    __syncthreads();
    mx = red[0];
    #pragma unroll
    for (int w = 1; w < 8; w++) mx = fmaxf(mx, red[w]);

    float s = 0.f;
    #pragma unroll
    for (int i = 0; i < 8; i++)
        s += __expf(v[i] - mx);
    #pragma unroll
    for (int o = 16; o; o >>= 1)
        s += __shfl_xor_sync(0xffffffffu, s, o);
    __syncthreads();
    if ((tid & 31) == 0) red[tid >> 5] = s;
    __syncthreads();
    s = red[0];
    #pragma unroll
    for (int w = 1; w < 8; w++) s += red[w];

    const float inv = 1.0f / s;
    #pragma unroll
    for (int i = 0; i < 8; i++)
        po[tid + i * 256] = __float2half_rn(__expf(v[i] - mx) * inv);
}

// ---------------------------------------------------------------------------
// Elementwise split: fp32 -> half hi/lo
// ---------------------------------------------------------------------------
__global__ __launch_bounds__(256)
void split_hl(const float* __restrict__ in, __half* __restrict__ oH,
              __half* __restrict__ oL, long n4)
{
    const long i = (long)blockIdx.x * 256 + threadIdx.x;
    if (i >= n4) return;
    float4 v = *(const float4*)(in + 4 * i);
    uint2 hh, ll;
    split2(v.x, v.y, hh.x, ll.x);
    split2(v.z, v.w, hh.y, ll.y);
    *(uint2*)(oH + 4 * i) = hh;
    *(uint2*)(oL + 4 * i) = ll;
}

// ---------------------------------------------------------------------------
// Transpose + split: in[R,C] fp32 -> oH/oL[C,R] half (square 512x512 weights).
// ---------------------------------------------------------------------------
__global__ __launch_bounds__(256)
void transpose_split(const float* __restrict__ in,
                     __half* __restrict__ oH, __half* __restrict__ oL,
                     int R, int C)
{
    __shared__ float t[32][33];
    const int tx = threadIdx.x & 31;
    const int ty = threadIdx.x >> 5;
    const int bx = blockIdx.x * 32;
    const int by = blockIdx.y * 32;
    #pragma unroll
    for (int jj = 0; jj < 4; jj++)
        t[ty + 8 * jj][tx] = in[(long)(by + ty + 8 * jj) * C + bx + tx];
    __syncthreads();
    #pragma unroll
    for (int jj = 0; jj < 4; jj++) {
        const float f = t[tx][ty + 8 * jj];
        const __half h = __float2half_rn(f);
        const __half l = __float2half_rn(f - __half2float(h));
        const long o = (long)(bx + ty + 8 * jj) * R + by + tx;
        oH[o] = h;
        oL[o] = l;
    }
}

// ---------------------------------------------------------------------------
// V transpose from strided qkv split layout: vt[b][d][s] = v[b][s][d]
// ---------------------------------------------------------------------------
__global__ __launch_bounds__(256)
void transpose_v(const __half* __restrict__ qkvH, const __half* __restrict__ qkvL,
                 __half* __restrict__ vtH, __half* __restrict__ vtL)
{
    __shared__ float t[32][33];
    const long inB  = (long)blockIdx.z * SEQ * NQKV;
    const long outB = (long)blockIdx.z * SEQ * DIM;
    const int tx = threadIdx.x & 31;
    const int ty = threadIdx.x >> 5;
    const int bx = blockIdx.x * 32;   // d base
    const int by = blockIdx.y * 32;   // s base
    #pragma unroll
    for (int jj = 0; jj < 4; jj++) {
        const long idx = inB + (long)(by + ty + 8 * jj) * NQKV + 1024 + bx + tx;
        t[ty + 8 * jj][tx] = __half2float(qkvH[idx]) + __half2float(qkvL[idx]);
    }
    __syncthreads();
    #pragma unroll
    for (int jj = 0; jj < 4; jj++) {
        const float f = t[tx][ty + 8 * jj];
        const __half h = __float2half_rn(f);
        const __half l = __float2half_rn(f - __half2float(h));
        const long o = outB + (long)(bx + ty + 8 * jj) * SEQ + by + tx;
        vtH[o] = h;
        vtL[o] = l;
    }
}

// ---------------------------------------------------------------------------
// Bias concat: [bq | bk | bv] -> g_bias[1536]
// ---------------------------------------------------------------------------
__global__ __launch_bounds__(256)
void concat_bias(const float* __restrict__ bq, const float* __restrict__ bk,
                 const float* __restrict__ bv, float* __restrict__ b)
{
    const int i = blockIdx.x * 256 + threadIdx.x;
    if (i < 512)       b[i] = bq[i];
    else if (i < 1024) b[i] = bk[i - 512];
    else if (i < 1536) b[i] = bv[i - 1024];
}

// ---------------------------------------------------------------------------
// Launch
// ---------------------------------------------------------------------------
extern "C" void kernel_launch(void* const* d_in, const int* in_sizes, int n_in,
                              void* d_out, int out_size)
{
    const float* x  = (const float*)d_in[0];
    const float* Wq = (const float*)d_in[1];
    const float* bq = (const float*)d_in[2];
    const float* Wk = (const float*)d_in[3];
    const float* bk = (const float*)d_in[4];
    const float* Wv = (const float*)d_in[5];
    const float* bv = (const float*)d_in[6];
    float* out = (float*)d_out;

    __half *xH, *xL, *wH, *wL, *qkvH, *qkvL, *vtH, *vtL, *pbuf;
    float *sim, *bias;
    cudaGetSymbolAddress((void**)&xH, g_xH);
    cudaGetSymbolAddress((void**)&xL, g_xL);
    cudaGetSymbolAddress((void**)&wH, g_wH);
    cudaGetSymbolAddress((void**)&wL, g_wL);
    cudaGetSymbolAddress((void**)&bias, g_bias);
    cudaGetSymbolAddress((void**)&qkvH, g_qkvH);
    cudaGetSymbolAddress((void**)&qkvL, g_qkvL);
    cudaGetSymbolAddress((void**)&vtH, g_vtH);
    cudaGetSymbolAddress((void**)&vtL, g_vtL);
    cudaGetSymbolAddress((void**)&sim, g_sim);
    cudaGetSymbolAddress((void**)&pbuf, g_p);

    cudaFuncSetAttribute(gemm_f16<0>,
                         cudaFuncAttributeMaxDynamicSharedMemorySize, SMEM_BYTES);
    cudaFuncSetAttribute(gemm_f16<1>,
                         cudaFuncAttributeMaxDynamicSharedMemorySize, SMEM_BYTES);
    cudaFuncSetAttribute(gemm_f16<2>,
                         cudaFuncAttributeMaxDynamicSharedMemorySize, SMEM_BYTES);

    // 0a) split x into half hi/lo
    {
        const long n4 = (long)MROWS * DIM / 4;
        split_hl<<<(unsigned)((n4 + 255) / 256), 256>>>(x, xH, xL, n4);
    }
    // 0b) transpose+split each weight into its [512,512] slab of [1536,512]
    {
        dim3 grid(DIM / 32, DIM / 32, 1);
        transpose_split<<<grid, 256>>>(Wq, wH, wL, DIM, DIM);
        transpose_split<<<grid, 256>>>(Wk, wH + (size_t)DIM * DIM,
                                       wL + (size_t)DIM * DIM, DIM, DIM);
        transpose_split<<<grid, 256>>>(Wv, wH + 2 * (size_t)DIM * DIM,
                                       wL + 2 * (size_t)DIM * DIM, DIM, DIM);
    }
    // 0c) bias concat
    concat_bias<<<6, 256>>>(bq, bk, bv, bias);

    // 1) Fused QKV projection: [32768,1536] = x @ [Wq|Wk|Wv]^T + bias.
    //    Q/K slabs (cols < 1024): x2 precision (drop xL term), no lo stores.
    //    V slab (cols >= 1024): full x3, split hi/lo output.
    {
        dim3 grid(NQKV / BN, MROWS / BM, 1);
        gemm_f16<1><<<grid, NTH, SMEM_BYTES>>>(xH, xL, wH, wL, bias,
                                               nullptr, qkvH, qkvL,
                                               MROWS, NQKV, DIM,
                                               DIM, DIM, NQKV,
                                               1.0f, 1, 1024, 1024, 0, 0, 0);
    }

    // 1b) transpose V slab -> vtH/vtL [b][d][s]
    {
        dim3 grid(DIM / 32, SEQ / 32, BATCH);
        transpose_v<<<grid, 256>>>(qkvH, qkvL, vtH, vtL);
    }

    // 2) sim[b] = Q[b] @ K[b]^T * SCALE (fp16 x1, hi parts only) -> fp32
    {
        dim3 grid(SEQ / BN, SEQ / BM, BATCH);
        gemm_f16<0><<<grid, NTH, SMEM_BYTES>>>(qkvH, nullptr,
                                               qkvH + 512, nullptr, nullptr,
                                               sim, nullptr, nullptr,
                                               SEQ, SEQ, DIM,
                                               NQKV, NQKV, SEQ,
                                               SCALE, 0, NQKV, 0,
                                               (long)SEQ * NQKV,
                                               (long)SEQ * NQKV,
                                               (long)SEQ * SEQ);
    }

    // 3) softmax -> P (fp16)
    softmax_p<<<MROWS, 256>>>(sim, pbuf);

    // 4) out[b] = P[b] @ Vt[b]^T  (X3=2: pH*vH + pH*vL), pure cp.async GEMM
    {
        dim3 grid(DIM / BN, SEQ / BM, BATCH);
        gemm_f16<2><<<grid, NTH, SMEM_BYTES>>>(pbuf, nullptr, vtH, vtL,
                                               nullptr, out, nullptr, nullptr,
                                               SEQ, DIM, SEQ,
                                               SEQ, SEQ, DIM,
                                               1.0f, 0, DIM, 0,
                                               (long)SEQ * SEQ,
                                               (long)DIM * SEQ,
                                               (long)SEQ * DIM);
    }
}